// round 11
// baseline (speedup 1.0000x reference)
#include <cuda_runtime.h>
#include <cuda_fp16.h>
#include <cstdint>
#include <math.h>

#define BB 32
#define CC 256
#define NN 1024
#define QCH 64
#define KCH 16
#define VCH 64
#define HEADS 4
#define KD 16
#define RR 23
#define PADL 11
#define EPSB 1e-5f

#if defined(__CUDA_ARCH_FEAT_SM103_ALL) || defined(__CUDA_ARCH_FEAT_SM100_ALL) || \
    defined(__CUDA_ARCH_FEAT_SM101_ALL) || defined(__CUDA_ARCH_SPECIFIC__) || \
    defined(__CUDA_ARCH_FAMILY_SPECIFIC__)
#define USE_TC 1
#else
#define USE_TC 0
#endif

// ---------------- scratch ----------------
__device__ float g_q[BB * QCH * NN];
__device__ float g_k[BB * KCH * NN];                   // raw (pre-softmax) k
__device__ float g_v[BB * VCH * NN];
__device__ __half g_lph[(size_t)BB * KD * NN * VCH];   // lambda_p fp16 [b][k][n][v]
__device__ float g_lcp[8][BB * KD * VCH];
__device__ float g_qs[QCH], g_qb[QCH];
__device__ float g_vs[VCH], g_vb[VCH];
__device__ float g_smx[BB * KD], g_smi[BB * KD];
// tiled + pre-swizzled operands (SW128 within each tile):
__device__ __align__(1024) __half g_T[(size_t)16 * 1024 * 1024];   // [k16][ch16][nt8] 16KB tiles
__device__ __align__(1024) __half g_vhs[(size_t)2048 * 1024];      // [ch16][bvt8] 32KB tiles
__device__ __half g_vh[(size_t)2048 * 1024];                       // linear for k_lambdac
__device__ __align__(1024) __half g_xh[(size_t)BB * NN * CC];      // [b][ch4][nt8] 16KB tiles
__device__ __align__(1024) __half g_wh[4 * 160 * 64];              // [ch4] 20KB tiles

// ---------------- PTX helpers ----------------
__device__ __forceinline__ uint32_t smem_u32(const void* p) {
    uint32_t r;
    asm("{ .reg .u64 t; cvta.to.shared.u64 t, %1; cvt.u32.u64 %0, t; }" : "=r"(r) : "l"(p));
    return r;
}
__device__ __forceinline__ void bulkcp(uint32_t dst, const void* src, uint32_t bytes, uint32_t mbar) {
    asm volatile("cp.async.bulk.shared::cluster.global.mbarrier::complete_tx::bytes [%0], [%1], %2, [%3];"
        :: "r"(dst), "l"(src), "r"(bytes), "r"(mbar) : "memory");
}
#define MBAR_INIT(a, c) asm volatile("mbarrier.init.shared.b64 [%0], %1;" :: "r"(a), "r"(c) : "memory")
#define MBAR_INVAL(a)   asm volatile("mbarrier.inval.shared.b64 [%0];" :: "r"(a) : "memory")
#define MBAR_EXPECT_TX(a, n) asm volatile("mbarrier.arrive.expect_tx.shared.b64 _, [%0], %1;" :: "r"(a), "r"(n) : "memory")
#define MBAR_WAIT(a, ph) do { \
    uint32_t _m = (a), _p = (ph), _d; \
    asm volatile("{ .reg .pred p; mbarrier.try_wait.parity.acquire.cta.shared::cta.b64 p, [%1], %2; selp.b32 %0,1,0,p; }" \
        : "=r"(_d) : "r"(_m), "r"(_p) : "memory"); \
    if (!_d) { \
        asm volatile("{ .reg .pred P1; WL_%=: mbarrier.try_wait.parity.acquire.cta.shared::cta.b64 P1, [%0], %1, 0x989680; @P1 bra.uni WD_%=; bra.uni WL_%=; WD_%=: }" \
            :: "r"(_m), "r"(_p) : "memory"); \
    } } while (0)

#if USE_TC
#define TC_ALLOC(sa, n)   asm volatile("tcgen05.alloc.cta_group::1.sync.aligned.shared::cta.b32 [%0], %1;" :: "r"(sa), "r"(n) : "memory")
#define TC_DEALLOC(t, n)  asm volatile("tcgen05.dealloc.cta_group::1.sync.aligned.b32 %0, %1;" :: "r"(t), "r"(n))
#define TC_RELINQ()       asm volatile("tcgen05.relinquish_alloc_permit.cta_group::1.sync.aligned;")
#define TC_COMMIT(mb)     asm volatile("tcgen05.commit.cta_group::1.mbarrier::arrive::one.shared::cluster.b64 [%0];" :: "r"(mb) : "memory")
#define TC_FENCE_AFTER()  asm volatile("tcgen05.fence::after_thread_sync;" ::: "memory")
#define TC_FENCE_BEFORE() asm volatile("tcgen05.fence::before_thread_sync;" ::: "memory")
#define TC_WAIT_LD()      asm volatile("tcgen05.wait::ld.sync.aligned;" ::: "memory")

#define TC_LD_X32(r, t) \
    asm volatile("tcgen05.ld.sync.aligned.32x32b.x32.b32 " \
        "{%0,%1,%2,%3,%4,%5,%6,%7,%8,%9,%10,%11,%12,%13,%14,%15," \
        "%16,%17,%18,%19,%20,%21,%22,%23,%24,%25,%26,%27,%28,%29,%30,%31}, [%32];" \
        : "=r"((r)[0]),"=r"((r)[1]),"=r"((r)[2]),"=r"((r)[3]),"=r"((r)[4]),"=r"((r)[5]),"=r"((r)[6]),"=r"((r)[7]), \
          "=r"((r)[8]),"=r"((r)[9]),"=r"((r)[10]),"=r"((r)[11]),"=r"((r)[12]),"=r"((r)[13]),"=r"((r)[14]),"=r"((r)[15]), \
          "=r"((r)[16]),"=r"((r)[17]),"=r"((r)[18]),"=r"((r)[19]),"=r"((r)[20]),"=r"((r)[21]),"=r"((r)[22]),"=r"((r)[23]), \
          "=r"((r)[24]),"=r"((r)[25]),"=r"((r)[26]),"=r"((r)[27]),"=r"((r)[28]),"=r"((r)[29]),"=r"((r)[30]),"=r"((r)[31]) \
        : "r"(t))

__device__ __forceinline__ void mma_f16_ss(uint32_t d, uint64_t ad, uint64_t bd,
                                           uint32_t idesc, uint32_t en) {
    asm volatile(
        "{ .reg .pred p; setp.ne.u32 p, %4, 0;\n\t"
        "tcgen05.mma.cta_group::1.kind::f16 [%0], %1, %2, %3, {%5,%5,%5,%5}, p;\n\t}"
        :: "r"(d), "l"(ad), "l"(bd), "r"(idesc), "r"(en), "r"(0u) : "memory");
}

static constexpr uint64_t DESC_BASE =
    (uint64_t(2) << 61) | (uint64_t(1) << 46) | (uint64_t(64) << 32) | (uint64_t(1) << 16);
__device__ __forceinline__ uint64_t mk_desc(uint32_t a) {
    return DESC_BASE | ((uint64_t)(a >> 4) & 0x3FFF);
}
#endif // USE_TC

__device__ __forceinline__ uint32_t sw128(uint32_t o) { return o ^ ((o >> 3) & 0x70); }

// ---------------- K0: merged prep (xhalf | whalf | buildT) ----------------
__global__ __launch_bounds__(256) void k_prep(
    const float* __restrict__ x, const float* __restrict__ Wq,
    const float* __restrict__ Wk, const float* __restrict__ Wv,
    const float* __restrict__ emb)
{
    int blk = blockIdx.x;
    int tid = threadIdx.x;
    if (blk < 2048) {
        int nt64 = blk & 15, ct = (blk >> 4) & 3, b = blk >> 6;
        int n0 = nt64 * 64, c0 = ct * 64;
        __shared__ float s[64][65];
        for (int i = tid; i < 64 * 64; i += 256) {
            int c = i >> 6, n = i & 63;
            s[c][n] = x[((size_t)b * 256 + c0 + c) * 1024 + n0 + n];
        }
        __syncthreads();
        int nt = n0 >> 7;
        char* tile = (char*)g_xh + (((size_t)b * 4 + ct) * 8 + nt) * 16384;
        for (int i = tid; i < 64 * 32; i += 256) {
            int nl64 = i >> 5, c2 = (i & 31) * 2;
            __half2 h = __floats2half2_rn(s[c2][nl64], s[c2 + 1][nl64]);
            int nl = (n0 & 127) + nl64;
            uint32_t o = sw128(nl * 128 + c2 * 2);
            *reinterpret_cast<__half2*>(tile + o) = h;
        }
    } else if (blk < 2208) {
        int i = (blk - 2048) * 256 + tid;
        int row = i >> 8, c = i & 255;
        float val;
        if (row < 64)       val = Wq[row * 256 + c];
        else if (row < 80)  val = Wk[(row - 64) * 256 + c];
        else if (row < 144) val = Wv[(row - 80) * 256 + c];
        else                val = 0.f;
        int ch = c >> 6, cl = c & 63;
        uint32_t o = sw128(row * 128 + cl * 2);
        *reinterpret_cast<__half*>((char*)g_wh + ch * 20480 + o) = __float2half(val);
    } else {
        size_t i = (size_t)(blk - 2208) * 256 + tid;
        int k = (int)(i >> 19);
        int rem = (int)(i & 0x7FFFF);
        int n = rem >> 9;
        int m0 = (rem & 511) * 2;
        int nt = n >> 7, nl = n & 127;
        int ch = m0 >> 6, ml = m0 & 63;
        {
            int y0t = nt * 4;
            int clo = (y0t > 11) ? ((y0t - 11) >> 1) : 0;
            int chi = min(15, (y0t + 14) >> 1);
            if (ch < clo || ch > chi) return;
        }
        int yn = n >> 5, xn = n & 31;
        float f[2];
        #pragma unroll
        for (int e = 0; e < 2; e++) {
            int mm = m0 + e;
            int dy = (mm >> 5) - yn + 11;
            int dx = (mm & 31) - xn + 11;
            f[e] = ((unsigned)dy < 23u && (unsigned)dx < 23u) ? emb[k * 529 + dy * 23 + dx] : 0.f;
        }
        __half2 h = __floats2half2_rn(f[0], f[1]);
        char* tile = (char*)g_T + (((size_t)k * 16 + ch) * 8 + nt) * 16384;
        *reinterpret_cast<__half2*>(tile + sw128(nl * 128 + ml * 2)) = h;
    }
}

// ---------------- K1: projections via bulk-copy + tcgen05 --------
#define PROJ_SMEM (1024 + 8 * 16384 + 4 * 20480)

__global__ __launch_bounds__(256) void k_proj()
{
#if USE_TC
    extern __shared__ char dsm[];
    __shared__ __align__(16) uint64_t s_full, s_mma;
    __shared__ uint32_t s_tmem;
    int tid = threadIdx.x;
    int wid = tid >> 5, lane = tid & 31;
    int b = blockIdx.y;
    int n0 = blockIdx.x * 256;

    uint32_t raw = smem_u32(dsm);
    uint32_t Ab = (raw + 1023) & ~1023u;
    uint32_t Bb = Ab + 8 * 16384;

    if (wid == 0) { TC_ALLOC(smem_u32(&s_tmem), 512); TC_RELINQ(); }
    if (tid == 0) { MBAR_INIT(smem_u32(&s_full), 1); MBAR_INIT(smem_u32(&s_mma), 1); }
    __syncthreads();
    uint32_t tmem = s_tmem;

    const uint32_t idesc = (1u << 4) | (20u << 17) | (8u << 24);  // F32 acc, f16, N=160, M=128
    if (tid == 0) {
        uint32_t fb = smem_u32(&s_full);
        MBAR_EXPECT_TX(fb, 8u * 16384u + 4u * 20480u);
        #pragma unroll
        for (int t = 0; t < 2; t++)
            #pragma unroll
            for (int c = 0; c < 4; c++)
                bulkcp(Ab + (t * 4 + c) * 16384,
                       (const char*)g_xh + (((size_t)b * 4 + c) * 8 + (blockIdx.x * 2 + t)) * 16384,
                       16384, fb);
        #pragma unroll
        for (int c = 0; c < 4; c++)
            bulkcp(Bb + c * 20480, (const char*)g_wh + c * 20480, 20480, fb);
        MBAR_WAIT(fb, 0);
        #pragma unroll
        for (int c = 0; c < 4; c++)
            #pragma unroll
            for (int t = 0; t < 2; t++) {
                uint64_t ad = mk_desc(Ab + (t * 4 + c) * 16384);
                uint64_t bd = mk_desc(Bb + c * 20480);
                #pragma unroll
                for (int ks = 0; ks < 4; ks++)
                    mma_f16_ss(tmem + t * 160, ad + ks * 2, bd + ks * 2, idesc, (c | ks) != 0);
            }
        TC_COMMIT(smem_u32(&s_mma));
    }
    MBAR_WAIT(smem_u32(&s_mma), 0);
    TC_FENCE_AFTER();

    int t = wid >> 2;
    int n_g = n0 + t * 128 + (wid & 3) * 32 + lane;
    for (int c0 = 0; c0 < 160; c0 += 32) {
        uint32_t r[32];
        TC_LD_X32(r, tmem + t * 160 + c0);
        TC_WAIT_LD();
        #pragma unroll
        for (int j = 0; j < 32; j++) {
            int ch = c0 + j;
            float val = __uint_as_float(r[j]);
            if (ch < 64)       g_q[(((size_t)b * 64 + ch) << 10) + n_g] = val;
            else if (ch < 80)  g_k[(((size_t)b * 16 + (ch - 64)) << 10) + n_g] = val;
            else if (ch < 144) g_v[(((size_t)b * 64 + (ch - 80)) << 10) + n_g] = val;
        }
    }
    __syncthreads();
    if (tid == 0) { MBAR_INVAL(smem_u32(&s_full)); MBAR_INVAL(smem_u32(&s_mma)); }
    __syncthreads();
    if (wid == 0) TC_DEALLOC(tmem, 512);
#else
    int b = blockIdx.y;
    int n = blockIdx.x * 256 + threadIdx.x;
    int nt = n >> 7, nl = n & 127;
    for (int ch = 0; ch < 144; ch++) {
        float acc = 0.f;
        for (int c = 0; c < 256; c++) {
            int cc = c >> 6, cl = c & 63;
            const char* at = (const char*)g_xh + (((size_t)b * 4 + cc) * 8 + nt) * 16384;
            const char* wt = (const char*)g_wh + cc * 20480;
            float xa = __half2float(*reinterpret_cast<const __half*>(at + sw128(nl * 128 + cl * 2)));
            float wa = __half2float(*reinterpret_cast<const __half*>(wt + sw128(ch * 128 + cl * 2)));
            acc += xa * wa;
        }
        if (ch < 64)       g_q[(((size_t)b * 64 + ch) << 10) + n] = acc;
        else if (ch < 80)  g_k[(((size_t)b * 16 + (ch - 64)) << 10) + n] = acc;
        else               g_v[(((size_t)b * 64 + (ch - 80)) << 10) + n] = acc;
    }
#endif
}

// ---------------- K2: merged stats: BN (blocks 0..127) + softmax (128..191) ---
__global__ __launch_bounds__(256) void k_stats(
    const float* __restrict__ bnw_q, const float* __restrict__ bnb_q,
    const float* __restrict__ bnw_v, const float* __restrict__ bnb_v)
{
    int blk = blockIdx.x;
    int tid = threadIdx.x;
    if (blk < 128) {
        int ch = blk;
        const float* src = (ch < 64) ? (g_q + (size_t)ch * NN) : (g_v + (size_t)(ch - 64) * NN);
        float s = 0.f, s2 = 0.f;
        for (int i = tid; i < BB * NN; i += 256) {
            int b = i >> 10, n = i & 1023;
            float v = src[((size_t)b * 64 << 10) + n];
            s += v; s2 += v * v;
        }
        __shared__ float rs[256], rs2[256];
        __shared__ float s_sc, s_sh;
        rs[tid] = s; rs2[tid] = s2;
        __syncthreads();
        for (int st = 128; st > 0; st >>= 1) {
            if (tid < st) { rs[tid] += rs[tid + st]; rs2[tid] += rs2[tid + st]; }
            __syncthreads();
        }
        if (tid == 0) {
            float inv = 1.f / (float)(BB * NN);
            float mean = rs[0] * inv;
            float var = rs2[0] * inv - mean * mean;
            float w, bsh;
            if (ch < 64) { w = bnw_q[ch]; bsh = bnb_q[ch]; }
            else         { w = bnw_v[ch - 64]; bsh = bnb_v[ch - 64]; }
            float sc = w * rsqrtf(var + EPSB);
            float sh = bsh - mean * sc;
            if (ch < 64) { g_qs[ch] = sc; g_qb[ch] = sh; }
            else         { g_vs[ch - 64] = sc; g_vb[ch - 64] = sh; }
            s_sc = sc; s_sh = sh;
        }
        __syncthreads();
        if (ch >= 64) {
            int v = ch - 64;
            float sc = s_sc, sh = s_sh;
            for (int i = tid; i < BB * NN; i += 256) {
                int b = i >> 10, n = i & 1023;
                float val = src[((size_t)b * 64 << 10) + n] * sc + sh;
                __half hv = __float2half(val);
                int bv = b * 64 + v;
                g_vh[(((size_t)bv) << 10) + n] = hv;
                int mch = n >> 6, ml = n & 63;
                int bvt = bv >> 8, bvl = bv & 255;
                char* tile = (char*)g_vhs + (((size_t)mch * 8 + bvt) * 32768);
                *reinterpret_cast<__half*>(tile + sw128(bvl * 128 + ml * 2)) = hv;
            }
        }
    } else {
        // softmax row stats: 64 blocks x 8 warps = 512 rows
        int row = (blk - 128) * 8 + (tid >> 5);
        int lane = tid & 31;
        const float* p = g_k + ((size_t)row << 10);
        float mx = -1e30f;
        for (int i = lane; i < 1024; i += 32) mx = fmaxf(mx, p[i]);
        #pragma unroll
        for (int o = 16; o; o >>= 1) mx = fmaxf(mx, __shfl_xor_sync(~0u, mx, o));
        float sm = 0.f;
        for (int i = lane; i < 1024; i += 32) sm += expf(p[i] - mx);
        #pragma unroll
        for (int o = 16; o; o >>= 1) sm += __shfl_xor_sync(~0u, sm, o);
        if (lane == 0) { g_smx[row] = mx; g_smi[row] = 1.f / sm; }
    }
}

// ---------------- K3: lambda_c partials ----------------
__global__ __launch_bounds__(256) void k_lambdac()
{
    int b = blockIdx.x;
    int part = blockIdx.y;
    int nc = part * 128;
    int tid = threadIdx.x;
    int s = tid >> 6, v = tid & 63;
    __shared__ float sbuf[16 * 128 + 128 * 65];
    __shared__ float s_mx[16], s_mi[16];
    float* sm_s = sbuf;
    float* vs_s = sbuf + 16 * 128;

    if (tid < 16) { s_mx[tid] = g_smx[b * 16 + tid]; s_mi[tid] = g_smi[b * 16 + tid]; }
    __syncthreads();

    for (int i = tid; i < 16 * 128; i += 256) {
        int k = i >> 7, nn = i & 127;
        float raw = g_k[(((size_t)b * 16 + k) << 10) + nc + nn];
        sm_s[k * 128 + nn] = expf(raw - s_mx[k]) * s_mi[k];
    }
    for (int i = tid; i < 64 * 128; i += 256) {
        int vv = i >> 7, nn = i & 127;
        vs_s[nn * 65 + vv] = __half2float(g_vh[(((size_t)b * 64 + vv) << 10) + nc + nn]);
    }
    __syncthreads();
    float acc[16] = {};
    for (int nn = s * 32; nn < s * 32 + 32; nn++) {
        float vv = vs_s[nn * 65 + v];
        #pragma unroll
        for (int k = 0; k < 16; k++) acc[k] += sm_s[k * 128 + nn] * vv;
    }
    __syncthreads();
    #pragma unroll
    for (int k = 0; k < 16; k++) sbuf[s * 1024 + k * 64 + v] = acc[k];
    __syncthreads();
    for (int e = tid; e < 1024; e += 256)
        g_lcp[part][b * 1024 + e] = sbuf[e] + sbuf[1024 + e] + sbuf[2048 + e] + sbuf[3072 + e];
}

// ---------------- K5: lambda_p GEMM — persistent over 4 kg, 1 wave ----------
// grid (8 ntb, 8 bvt, 2 kgp) = 128 CTAs. Each loops kg = kgp*4 + 0..3.
// Continuous 3-stage pipeline across kg boundaries; epilogue overlaps next loads.
#define GEMM_SMEM (1024 + 3 * 65536)

__global__ __launch_bounds__(256) void k_gemm(const float* __restrict__ emb)
{
#if USE_TC
    extern __shared__ char dsm[];
    __shared__ __align__(16) uint64_t s_full[3], s_mma[3];
    __shared__ uint32_t s_tmem;

    int tid = threadIdx.x;
    int wid = tid >> 5, lane = tid & 31;
    int kgp = blockIdx.z;
    int ntb = blockIdx.x;
    int bvt = blockIdx.y;
    int n0 = ntb * 128;
    int bv0 = bvt * 256;

    int y0 = ntb * 4;
    int c_lo = (y0 > 11) ? ((y0 - 11) >> 1) : 0;
    int c_hi = min(15, (y0 + 14) >> 1);
    int nch = c_hi - c_lo + 1;     // 8..14
    int gtot = 4 * nch;

    uint32_t raw = smem_u32(dsm);
    uint32_t abase = (raw + 1023) & ~1023u;

    if (wid == 0) { TC_ALLOC(smem_u32(&s_tmem), 512); TC_RELINQ(); }
    if (tid == 0) {
        #pragma unroll
        for (int s = 0; s < 3; s++) { MBAR_INIT(smem_u32(&s_full[s]), 1); MBAR_INIT(smem_u32(&s_mma[s]), 1); }
    }
    __syncthreads();
    uint32_t tmem = s_tmem;

    const uint32_t idesc = (1u << 4) | (32u << 17) | (8u << 24);  // F32 acc, f16, N=256, M=128
    const char* Tb = (const char*)g_T;
    const char* Vb = (const char*)g_vhs;

    int fph[3] = {0, 0, 0}, mph[3] = {0, 0, 0};

    // load global chunk g into stage g%3 (chunk = c_lo + g%nch, kg = kgp*4 + g/nch)
    #define GEMM_LOAD(g) do {                                                             \
        int _g = (g);                                                                     \
        int _s = _g % 3;                                                                  \
        int _kg = kgp * 4 + _g / nch;                                                     \
        int _ch = c_lo + _g % nch;                                                        \
        uint32_t _fb = smem_u32(&s_full[_s]);                                             \
        uint32_t _sb = abase + _s * 65536;                                                \
        MBAR_EXPECT_TX(_fb, 65536u);                                                      \
        bulkcp(_sb,         Tb + (((size_t)(2 * _kg)     * 16 + _ch) * 8 + ntb) * 16384, 16384, _fb); \
        bulkcp(_sb + 16384, Tb + (((size_t)(2 * _kg + 1) * 16 + _ch) * 8 + ntb) * 16384, 16384, _fb); \
        bulkcp(_sb + 32768, Vb + (((size_t)_ch * 8 + bvt) * 32768), 32768, _fb);          \
    } while (0)

    if (tid == 0) { GEMM_LOAD(0); GEMM_LOAD(1); GEMM_LOAD(2); }

    for (int kg_i = 0; kg_i < 4; kg_i++) {
        if (tid == 0) {
            for (int ci = 0; ci < nch; ci++) {
                int g = kg_i * nch + ci;
                int s = g % 3;
                MBAR_WAIT(smem_u32(&s_full[s]), fph[s]); fph[s] ^= 1;
                uint32_t sb = abase + s * 65536;
                uint64_t a0 = mk_desc(sb);
                uint64_t a1 = mk_desc(sb + 16384);
                uint64_t bd = mk_desc(sb + 32768);
                #pragma unroll
                for (int ks = 0; ks < 4; ks++) {
                    uint32_t en = (ci | ks) != 0;
                    mma_f16_ss(tmem,       a0 + ks * 2, bd + ks * 2, idesc, en);
                    mma_f16_ss(tmem + 256, a1 + ks * 2, bd + ks * 2, idesc, en);
                }
                TC_COMMIT(smem_u32(&s_mma[s]));
                if (g + 3 < gtot) {
                    MBAR_WAIT(smem_u32(&s_mma[s]), mph[s]); mph[s] ^= 1;
                    GEMM_LOAD(g + 3);
                }
            }
            if (kg_i == 3) {
                // last 3 global chunks' commits un-waited: drain all stages
                MBAR_WAIT(smem_u32(&s_mma[0]), mph[0]);
                MBAR_WAIT(smem_u32(&s_mma[1]), mph[1]);
                MBAR_WAIT(smem_u32(&s_mma[2]), mph[2]);
            }
            // for kg_i<3: the in-loop wait on chunk (kg_i+1)*nch-1 already drained this kg
        }
        __syncthreads();
        TC_FENCE_AFTER();

        // epilogue for this kg: two D tiles -> g_lph fp16 [b][k][n][v]
        int t = wid >> 2;
        int kk = 2 * (kgp * 4 + kg_i) + t;
        int n_g = n0 + (wid & 3) * 32 + lane;
        for (int c0 = 0; c0 < 256; c0 += 32) {
            uint32_t r[32];
            TC_LD_X32(r, tmem + t * 256 + c0);
            TC_WAIT_LD();
            int bvb = bv0 + c0;
            int b = bvb >> 6, vb = bvb & 63;
            uint32_t h2[16];
            #pragma unroll
            for (int j = 0; j < 16; j++) {
                __half2 h = __floats2half2_rn(__uint_as_float(r[2 * j]), __uint_as_float(r[2 * j + 1]));
                h2[j] = *reinterpret_cast<uint32_t*>(&h);
            }
            __half* dst = g_lph + ((((size_t)(b * 16 + kk) << 10) + n_g) << 6) + vb;
            uint4* d4 = reinterpret_cast<uint4*>(dst);
            #pragma unroll
            for (int q4 = 0; q4 < 4; q4++)
                d4[q4] = make_uint4(h2[4 * q4], h2[4 * q4 + 1], h2[4 * q4 + 2], h2[4 * q4 + 3]);
        }
        TC_FENCE_BEFORE();
        __syncthreads();   // TMEM reads done before next kg's MMAs overwrite D
    }

    if (tid == 0) {
        #pragma unroll
        for (int s = 0; s < 3; s++) { MBAR_INVAL(smem_u32(&s_full[s])); MBAR_INVAL(smem_u32(&s_mma[s])); }
    }
    __syncthreads();
    if (wid == 0) TC_DEALLOC(tmem, 512);
    #undef GEMM_LOAD

#else  // ---- fallback: scalar direct conv (compile-only; grid 8x8x2 = 128 blocks) ----
    extern __shared__ char dsm[];
    float* img = (float*)dsm;
    float* Es  = img + 54 * 55;
    int tid = threadIdx.x;
    int bid = blockIdx.x + blockIdx.y * 8 + blockIdx.z * 64;   // 0..127

    for (int i = tid; i < 16 * 529; i += 256) Es[i] = emb[i];

    for (int pair = 0; pair < 16; pair++) {
        int bv = bid * 16 + pair;
        int b = bv >> 6, v = bv & 63;
        __syncthreads();
        for (int i = tid; i < 54 * 55; i += 256) img[i] = 0.f;
        __syncthreads();
        float vsc = g_vs[v], vsh = g_vb[v];
        const float* src = g_v + ((size_t)bv << 10);
        for (int i = tid; i < 1024; i += 256) {
            int y = i >> 5, x = i & 31;
            img[(y + PADL) * 55 + x + PADL] = src[i] * vsc + vsh;
        }
        __syncthreads();

        for (int it = 0; it < 4; it++) {
            int task = tid + 256 * it;
            int k = task >> 6;
            int rh = task & 63;
            int row = rh >> 1;
            int xb = (rh & 1) << 4;
            float acc[16] = {};
            const float* ek = Es + k * 529;
            #pragma unroll 1
            for (int i = 0; i < RR; i++) {
                const float* rp = img + (row + i) * 55 + xb;
                float r[38];
                #pragma unroll
                for (int tt = 0; tt < 38; tt++) r[tt] = rp[tt];
                const float* ept = ek + i * RR;
                #pragma unroll
                for (int j = 0; j < RR; j++) {
                    float e = ept[j];
                    #pragma unroll
                    for (int x = 0; x < 16; x++) acc[x] += e * r[j + x];
                }
            }
            int nbase = row * 32 + xb;
            __half* o = g_lph + ((((size_t)(b * 16 + k) << 10) + nbase) << 6) + v;
            #pragma unroll
            for (int x = 0; x < 16; x++) o[(size_t)x << 6] = __float2half(acc[x]);
        }
    }
#endif
}

// ---------------- K6: final contraction (lambda_c reduce fused in) -----------
__global__ __launch_bounds__(256) void k_final(const float* __restrict__ gamma,
                                               float* __restrict__ out)
{
    int b = blockIdx.z;
    int v0 = blockIdx.y * 16;
    int n = blockIdx.x * 256 + threadIdx.x;
    __shared__ float lc_s[256];
    for (int i = threadIdx.x; i < 256; i += 256) {
        int idx = b * 1024 + (i >> 4) * 64 + v0 + (i & 15);
        float sum = 0.f;
        #pragma unroll
        for (int p = 0; p < 8; p++) sum += g_lcp[p][idx];
        lc_s[i] = sum;
    }
    __syncthreads();
    float qv[64];
    #pragma unroll
    for (int ch = 0; ch < 64; ch++)
        qv[ch] = g_q[(((size_t)b * 64 + ch) << 10) + n] * g_qs[ch] + g_qb[ch];
    float gm = 1.f + gamma[0];
    float y[4][16] = {};
    for (int k = 0; k < 16; k++) {
        const __half2* lp = reinterpret_cast<const __half2*>(
            g_lph + ((((size_t)(b * 16 + k) << 10) + n) << 6) + v0);
        float lam[16];
        #pragma unroll
        for (int j = 0; j < 8; j++) {
            float2 f = __half22float2(lp[j]);
            lam[2 * j] = f.x; lam[2 * j + 1] = f.y;
        }
        #pragma unroll
        for (int jj = 0; jj < 16; jj++) lam[jj] += lc_s[k * 16 + jj];
        #pragma unroll
        for (int h = 0; h < 4; h++) {
            float qh = qv[h * 16 + k];
            #pragma unroll
            for (int jj = 0; jj < 16; jj++) y[h][jj] += qh * lam[jj];
        }
    }
    #pragma unroll
    for (int h = 0; h < 4; h++)
        #pragma unroll
        for (int jj = 0; jj < 16; jj++)
            out[(((size_t)b * 256) + h * 64 + v0 + jj) * NN + n] = y[h][jj] * gm;
}

// ---------------- launch ----------------
extern "C" void kernel_launch(void* const* d_in, const int* in_sizes, int n_in,
                              void* d_out, int out_size)
{
    const float* x      = (const float*)d_in[0];
    const float* Wq     = (const float*)d_in[1];
    const float* bn_q_w = (const float*)d_in[2];
    const float* bn_q_b = (const float*)d_in[3];
    const float* Wk     = (const float*)d_in[4];
    const float* Wv     = (const float*)d_in[5];
    const float* bn_v_w = (const float*)d_in[6];
    const float* bn_v_b = (const float*)d_in[7];
    const float* emb    = (const float*)d_in[8];
    const float* gamma  = (const float*)d_in[9];
    float* out = (float*)d_out;

    cudaFuncSetAttribute(k_gemm, cudaFuncAttributeMaxDynamicSharedMemorySize, GEMM_SMEM);
    cudaFuncSetAttribute(k_proj, cudaFuncAttributeMaxDynamicSharedMemorySize, PROJ_SMEM);

    k_prep<<<34976, 256>>>(x, Wq, Wk, Wv, emb);              // 1
    k_proj<<<dim3(4, 32), 256, PROJ_SMEM>>>();               // 2
    k_stats<<<192, 256>>>(bn_q_w, bn_q_b, bn_v_w, bn_v_b);   // 3
    k_gemm<<<dim3(8, 8, 2), 256, GEMM_SMEM>>>(emb);          // 4  <-- profiled slot
    k_lambdac<<<dim3(32, 8), 256>>>();                       // 5
    k_final<<<dim3(4, 4, 32), 256>>>(gamma, out);            // 6
}

// round 12
// speedup vs baseline: 1.0426x; 1.0426x over previous
#include <cuda_runtime.h>
#include <cuda_fp16.h>
#include <cstdint>
#include <math.h>

#define BB 32
#define CC 256
#define NN 1024
#define QCH 64
#define KCH 16
#define VCH 64
#define HEADS 4
#define KD 16
#define RR 23
#define PADL 11
#define EPSB 1e-5f

#if defined(__CUDA_ARCH_FEAT_SM103_ALL) || defined(__CUDA_ARCH_FEAT_SM100_ALL) || \
    defined(__CUDA_ARCH_FEAT_SM101_ALL) || defined(__CUDA_ARCH_SPECIFIC__) || \
    defined(__CUDA_ARCH_FAMILY_SPECIFIC__)
#define USE_TC 1
#else
#define USE_TC 0
#endif

// ---------------- scratch ----------------
__device__ float g_q[BB * QCH * NN];
__device__ float g_k[BB * KCH * NN];                   // raw (pre-softmax) k
__device__ float g_v[BB * VCH * NN];
__device__ __half g_qh[BB * QCH * NN];                 // BN'd q fp16 [b][ch][n]
__device__ __half g_lph[(size_t)BB * KD * NN * VCH];   // lambda_p fp16 [b][k][n][v]
__device__ float g_lcp[8][BB * KD * VCH];
__device__ float g_qs[QCH], g_qb[QCH];
__device__ float g_vs[VCH], g_vb[VCH];
__device__ float g_smx[BB * KD], g_smi[BB * KD];
// tiled + pre-swizzled operands (SW128 within each tile):
__device__ __align__(1024) __half g_T[(size_t)16 * 1024 * 1024];   // [k16][ch16][nt8] 16KB tiles
__device__ __align__(1024) __half g_vhs[(size_t)2048 * 1024];      // [ch16][bvt8] 32KB tiles
__device__ __half g_vh[(size_t)2048 * 1024];                       // linear for k_lambdac
__device__ __align__(1024) __half g_xh[(size_t)BB * NN * CC];      // [b][ch4][nt8] 16KB tiles
__device__ __align__(1024) __half g_wh[4 * 160 * 64];              // [ch4] 20KB tiles

// ---------------- PTX helpers ----------------
__device__ __forceinline__ uint32_t smem_u32(const void* p) {
    uint32_t r;
    asm("{ .reg .u64 t; cvta.to.shared.u64 t, %1; cvt.u32.u64 %0, t; }" : "=r"(r) : "l"(p));
    return r;
}
__device__ __forceinline__ void bulkcp(uint32_t dst, const void* src, uint32_t bytes, uint32_t mbar) {
    asm volatile("cp.async.bulk.shared::cluster.global.mbarrier::complete_tx::bytes [%0], [%1], %2, [%3];"
        :: "r"(dst), "l"(src), "r"(bytes), "r"(mbar) : "memory");
}
#define MBAR_INIT(a, c) asm volatile("mbarrier.init.shared.b64 [%0], %1;" :: "r"(a), "r"(c) : "memory")
#define MBAR_INVAL(a)   asm volatile("mbarrier.inval.shared.b64 [%0];" :: "r"(a) : "memory")
#define MBAR_EXPECT_TX(a, n) asm volatile("mbarrier.arrive.expect_tx.shared.b64 _, [%0], %1;" :: "r"(a), "r"(n) : "memory")
#define MBAR_WAIT(a, ph) do { \
    uint32_t _m = (a), _p = (ph), _d; \
    asm volatile("{ .reg .pred p; mbarrier.try_wait.parity.acquire.cta.shared::cta.b64 p, [%1], %2; selp.b32 %0,1,0,p; }" \
        : "=r"(_d) : "r"(_m), "r"(_p) : "memory"); \
    if (!_d) { \
        asm volatile("{ .reg .pred P1; WL_%=: mbarrier.try_wait.parity.acquire.cta.shared::cta.b64 P1, [%0], %1, 0x989680; @P1 bra.uni WD_%=; bra.uni WL_%=; WD_%=: }" \
            :: "r"(_m), "r"(_p) : "memory"); \
    } } while (0)

#if USE_TC
#define TC_ALLOC(sa, n)   asm volatile("tcgen05.alloc.cta_group::1.sync.aligned.shared::cta.b32 [%0], %1;" :: "r"(sa), "r"(n) : "memory")
#define TC_DEALLOC(t, n)  asm volatile("tcgen05.dealloc.cta_group::1.sync.aligned.b32 %0, %1;" :: "r"(t), "r"(n))
#define TC_RELINQ()       asm volatile("tcgen05.relinquish_alloc_permit.cta_group::1.sync.aligned;")
#define TC_COMMIT(mb)     asm volatile("tcgen05.commit.cta_group::1.mbarrier::arrive::one.shared::cluster.b64 [%0];" :: "r"(mb) : "memory")
#define TC_FENCE_AFTER()  asm volatile("tcgen05.fence::after_thread_sync;" ::: "memory")
#define TC_WAIT_LD()      asm volatile("tcgen05.wait::ld.sync.aligned;" ::: "memory")

#define TC_LD_X32(r, t) \
    asm volatile("tcgen05.ld.sync.aligned.32x32b.x32.b32 " \
        "{%0,%1,%2,%3,%4,%5,%6,%7,%8,%9,%10,%11,%12,%13,%14,%15," \
        "%16,%17,%18,%19,%20,%21,%22,%23,%24,%25,%26,%27,%28,%29,%30,%31}, [%32];" \
        : "=r"((r)[0]),"=r"((r)[1]),"=r"((r)[2]),"=r"((r)[3]),"=r"((r)[4]),"=r"((r)[5]),"=r"((r)[6]),"=r"((r)[7]), \
          "=r"((r)[8]),"=r"((r)[9]),"=r"((r)[10]),"=r"((r)[11]),"=r"((r)[12]),"=r"((r)[13]),"=r"((r)[14]),"=r"((r)[15]), \
          "=r"((r)[16]),"=r"((r)[17]),"=r"((r)[18]),"=r"((r)[19]),"=r"((r)[20]),"=r"((r)[21]),"=r"((r)[22]),"=r"((r)[23]), \
          "=r"((r)[24]),"=r"((r)[25]),"=r"((r)[26]),"=r"((r)[27]),"=r"((r)[28]),"=r"((r)[29]),"=r"((r)[30]),"=r"((r)[31]) \
        : "r"(t))

__device__ __forceinline__ void mma_f16_ss(uint32_t d, uint64_t ad, uint64_t bd,
                                           uint32_t idesc, uint32_t en) {
    asm volatile(
        "{ .reg .pred p; setp.ne.u32 p, %4, 0;\n\t"
        "tcgen05.mma.cta_group::1.kind::f16 [%0], %1, %2, %3, {%5,%5,%5,%5}, p;\n\t}"
        :: "r"(d), "l"(ad), "l"(bd), "r"(idesc), "r"(en), "r"(0u) : "memory");
}

static constexpr uint64_t DESC_BASE =
    (uint64_t(2) << 61) | (uint64_t(1) << 46) | (uint64_t(64) << 32) | (uint64_t(1) << 16);
__device__ __forceinline__ uint64_t mk_desc(uint32_t a) {
    return DESC_BASE | ((uint64_t)(a >> 4) & 0x3FFF);
}
#endif // USE_TC

__device__ __forceinline__ uint32_t sw128(uint32_t o) { return o ^ ((o >> 3) & 0x70); }

// ---------------- K0: merged prep (xhalf | whalf | buildT) ----------------
__global__ __launch_bounds__(256) void k_prep(
    const float* __restrict__ x, const float* __restrict__ Wq,
    const float* __restrict__ Wk, const float* __restrict__ Wv,
    const float* __restrict__ emb)
{
    int blk = blockIdx.x;
    int tid = threadIdx.x;
    if (blk < 2048) {
        int nt64 = blk & 15, ct = (blk >> 4) & 3, b = blk >> 6;
        int n0 = nt64 * 64, c0 = ct * 64;
        __shared__ float s[64][65];
        for (int i = tid; i < 64 * 64; i += 256) {
            int c = i >> 6, n = i & 63;
            s[c][n] = x[((size_t)b * 256 + c0 + c) * 1024 + n0 + n];
        }
        __syncthreads();
        int nt = n0 >> 7;
        char* tile = (char*)g_xh + (((size_t)b * 4 + ct) * 8 + nt) * 16384;
        for (int i = tid; i < 64 * 32; i += 256) {
            int nl64 = i >> 5, c2 = (i & 31) * 2;
            __half2 h = __floats2half2_rn(s[c2][nl64], s[c2 + 1][nl64]);
            int nl = (n0 & 127) + nl64;
            uint32_t o = sw128(nl * 128 + c2 * 2);
            *reinterpret_cast<__half2*>(tile + o) = h;
        }
    } else if (blk < 2208) {
        int i = (blk - 2048) * 256 + tid;
        int row = i >> 8, c = i & 255;
        float val;
        if (row < 64)       val = Wq[row * 256 + c];
        else if (row < 80)  val = Wk[(row - 64) * 256 + c];
        else if (row < 144) val = Wv[(row - 80) * 256 + c];
        else                val = 0.f;
        int ch = c >> 6, cl = c & 63;
        uint32_t o = sw128(row * 128 + cl * 2);
        *reinterpret_cast<__half*>((char*)g_wh + ch * 20480 + o) = __float2half(val);
    } else {
        size_t i = (size_t)(blk - 2208) * 256 + tid;
        int k = (int)(i >> 19);
        int rem = (int)(i & 0x7FFFF);
        int n = rem >> 9;
        int m0 = (rem & 511) * 2;
        int nt = n >> 7, nl = n & 127;
        int ch = m0 >> 6, ml = m0 & 63;
        {
            int y0t = nt * 4;
            int clo = (y0t > 11) ? ((y0t - 11) >> 1) : 0;
            int chi = min(15, (y0t + 14) >> 1);
            if (ch < clo || ch > chi) return;
        }
        int yn = n >> 5, xn = n & 31;
        float f[2];
        #pragma unroll
        for (int e = 0; e < 2; e++) {
            int mm = m0 + e;
            int dy = (mm >> 5) - yn + 11;
            int dx = (mm & 31) - xn + 11;
            f[e] = ((unsigned)dy < 23u && (unsigned)dx < 23u) ? emb[k * 529 + dy * 23 + dx] : 0.f;
        }
        __half2 h = __floats2half2_rn(f[0], f[1]);
        char* tile = (char*)g_T + (((size_t)k * 16 + ch) * 8 + nt) * 16384;
        *reinterpret_cast<__half2*>(tile + sw128(nl * 128 + ml * 2)) = h;
    }
}

// ---------------- K1: projections via bulk-copy + tcgen05 --------
#define PROJ_SMEM (1024 + 8 * 16384 + 4 * 20480)

__global__ __launch_bounds__(256) void k_proj()
{
#if USE_TC
    extern __shared__ char dsm[];
    __shared__ __align__(16) uint64_t s_full, s_mma;
    __shared__ uint32_t s_tmem;
    int tid = threadIdx.x;
    int wid = tid >> 5, lane = tid & 31;
    int b = blockIdx.y;
    int n0 = blockIdx.x * 256;

    uint32_t raw = smem_u32(dsm);
    uint32_t Ab = (raw + 1023) & ~1023u;
    uint32_t Bb = Ab + 8 * 16384;

    if (wid == 0) { TC_ALLOC(smem_u32(&s_tmem), 512); TC_RELINQ(); }
    if (tid == 0) { MBAR_INIT(smem_u32(&s_full), 1); MBAR_INIT(smem_u32(&s_mma), 1); }
    __syncthreads();
    uint32_t tmem = s_tmem;

    const uint32_t idesc = (1u << 4) | (20u << 17) | (8u << 24);  // F32 acc, f16, N=160, M=128
    if (tid == 0) {
        uint32_t fb = smem_u32(&s_full);
        MBAR_EXPECT_TX(fb, 8u * 16384u + 4u * 20480u);
        #pragma unroll
        for (int t = 0; t < 2; t++)
            #pragma unroll
            for (int c = 0; c < 4; c++)
                bulkcp(Ab + (t * 4 + c) * 16384,
                       (const char*)g_xh + (((size_t)b * 4 + c) * 8 + (blockIdx.x * 2 + t)) * 16384,
                       16384, fb);
        #pragma unroll
        for (int c = 0; c < 4; c++)
            bulkcp(Bb + c * 20480, (const char*)g_wh + c * 20480, 20480, fb);
        MBAR_WAIT(fb, 0);
        #pragma unroll
        for (int c = 0; c < 4; c++)
            #pragma unroll
            for (int t = 0; t < 2; t++) {
                uint64_t ad = mk_desc(Ab + (t * 4 + c) * 16384);
                uint64_t bd = mk_desc(Bb + c * 20480);
                #pragma unroll
                for (int ks = 0; ks < 4; ks++)
                    mma_f16_ss(tmem + t * 160, ad + ks * 2, bd + ks * 2, idesc, (c | ks) != 0);
            }
        TC_COMMIT(smem_u32(&s_mma));
    }
    MBAR_WAIT(smem_u32(&s_mma), 0);
    TC_FENCE_AFTER();

    int t = wid >> 2;
    int n_g = n0 + t * 128 + (wid & 3) * 32 + lane;
    for (int c0 = 0; c0 < 160; c0 += 32) {
        uint32_t r[32];
        TC_LD_X32(r, tmem + t * 160 + c0);
        TC_WAIT_LD();
        #pragma unroll
        for (int j = 0; j < 32; j++) {
            int ch = c0 + j;
            float val = __uint_as_float(r[j]);
            if (ch < 64)       g_q[(((size_t)b * 64 + ch) << 10) + n_g] = val;
            else if (ch < 80)  g_k[(((size_t)b * 16 + (ch - 64)) << 10) + n_g] = val;
            else if (ch < 144) g_v[(((size_t)b * 64 + (ch - 80)) << 10) + n_g] = val;
        }
    }
    __syncthreads();
    if (tid == 0) { MBAR_INVAL(smem_u32(&s_full)); MBAR_INVAL(smem_u32(&s_mma)); }
    __syncthreads();
    if (wid == 0) TC_DEALLOC(tmem, 512);
#else
    int b = blockIdx.y;
    int n = blockIdx.x * 256 + threadIdx.x;
    int nt = n >> 7, nl = n & 127;
    for (int ch = 0; ch < 144; ch++) {
        float acc = 0.f;
        for (int c = 0; c < 256; c++) {
            int cc = c >> 6, cl = c & 63;
            const char* at = (const char*)g_xh + (((size_t)b * 4 + cc) * 8 + nt) * 16384;
            const char* wt = (const char*)g_wh + cc * 20480;
            float xa = __half2float(*reinterpret_cast<const __half*>(at + sw128(nl * 128 + cl * 2)));
            float wa = __half2float(*reinterpret_cast<const __half*>(wt + sw128(ch * 128 + cl * 2)));
            acc += xa * wa;
        }
        if (ch < 64)       g_q[(((size_t)b * 64 + ch) << 10) + n] = acc;
        else if (ch < 80)  g_k[(((size_t)b * 16 + (ch - 64)) << 10) + n] = acc;
        else               g_v[(((size_t)b * 64 + (ch - 80)) << 10) + n] = acc;
    }
#endif
}

// ---------------- K2: merged stats: BN (0..127) + softmax (128..191) ----------
// BN q channels additionally write BN'd fp16 q (g_qh); v channels write g_vh/g_vhs.
__global__ __launch_bounds__(256) void k_stats(
    const float* __restrict__ bnw_q, const float* __restrict__ bnb_q,
    const float* __restrict__ bnw_v, const float* __restrict__ bnb_v)
{
    int blk = blockIdx.x;
    int tid = threadIdx.x;
    if (blk < 128) {
        int ch = blk;
        const float* src = (ch < 64) ? (g_q + (size_t)ch * NN) : (g_v + (size_t)(ch - 64) * NN);
        float s = 0.f, s2 = 0.f;
        for (int i = tid; i < BB * NN; i += 256) {
            int b = i >> 10, n = i & 1023;
            float v = src[((size_t)b * 64 << 10) + n];
            s += v; s2 += v * v;
        }
        __shared__ float rs[256], rs2[256];
        __shared__ float s_sc, s_sh;
        rs[tid] = s; rs2[tid] = s2;
        __syncthreads();
        for (int st = 128; st > 0; st >>= 1) {
            if (tid < st) { rs[tid] += rs[tid + st]; rs2[tid] += rs2[tid + st]; }
            __syncthreads();
        }
        if (tid == 0) {
            float inv = 1.f / (float)(BB * NN);
            float mean = rs[0] * inv;
            float var = rs2[0] * inv - mean * mean;
            float w, bsh;
            if (ch < 64) { w = bnw_q[ch]; bsh = bnb_q[ch]; }
            else         { w = bnw_v[ch - 64]; bsh = bnb_v[ch - 64]; }
            float sc = w * rsqrtf(var + EPSB);
            float sh = bsh - mean * sc;
            if (ch < 64) { g_qs[ch] = sc; g_qb[ch] = sh; }
            else         { g_vs[ch - 64] = sc; g_vb[ch - 64] = sh; }
            s_sc = sc; s_sh = sh;
        }
        __syncthreads();
        float sc = s_sc, sh = s_sh;
        if (ch < 64) {
            // BN'd q -> fp16, same [b][ch][n] layout (coalesced)
            for (int i = tid; i < BB * NN; i += 256) {
                int b = i >> 10, n = i & 1023;
                float val = src[((size_t)b * 64 << 10) + n] * sc + sh;
                g_qh[(((size_t)(b * 64 + ch)) << 10) + n] = __float2half(val);
            }
        } else {
            int v = ch - 64;
            for (int i = tid; i < BB * NN; i += 256) {
                int b = i >> 10, n = i & 1023;
                float val = src[((size_t)b * 64 << 10) + n] * sc + sh;
                __half hv = __float2half(val);
                int bv = b * 64 + v;
                g_vh[(((size_t)bv) << 10) + n] = hv;
                int mch = n >> 6, ml = n & 63;
                int bvt = bv >> 8, bvl = bv & 255;
                char* tile = (char*)g_vhs + (((size_t)mch * 8 + bvt) * 32768);
                *reinterpret_cast<__half*>(tile + sw128(bvl * 128 + ml * 2)) = hv;
            }
        }
    } else {
        // softmax row stats: 64 blocks x 8 warps = 512 rows
        int row = (blk - 128) * 8 + (tid >> 5);
        int lane = tid & 31;
        const float* p = g_k + ((size_t)row << 10);
        float mx = -1e30f;
        for (int i = lane; i < 1024; i += 32) mx = fmaxf(mx, p[i]);
        #pragma unroll
        for (int o = 16; o; o >>= 1) mx = fmaxf(mx, __shfl_xor_sync(~0u, mx, o));
        float sm = 0.f;
        for (int i = lane; i < 1024; i += 32) sm += expf(p[i] - mx);
        #pragma unroll
        for (int o = 16; o; o >>= 1) sm += __shfl_xor_sync(~0u, sm, o);
        if (lane == 0) { g_smx[row] = mx; g_smi[row] = 1.f / sm; }
    }
}

// ---------------- K3: lambda_c partials ----------------
__global__ __launch_bounds__(256) void k_lambdac()
{
    int b = blockIdx.x;
    int part = blockIdx.y;
    int nc = part * 128;
    int tid = threadIdx.x;
    int s = tid >> 6, v = tid & 63;
    __shared__ float sbuf[16 * 128 + 128 * 65];
    __shared__ float s_mx[16], s_mi[16];
    float* sm_s = sbuf;
    float* vs_s = sbuf + 16 * 128;

    if (tid < 16) { s_mx[tid] = g_smx[b * 16 + tid]; s_mi[tid] = g_smi[b * 16 + tid]; }
    __syncthreads();

    for (int i = tid; i < 16 * 128; i += 256) {
        int k = i >> 7, nn = i & 127;
        float raw = g_k[(((size_t)b * 16 + k) << 10) + nc + nn];
        sm_s[k * 128 + nn] = expf(raw - s_mx[k]) * s_mi[k];
    }
    for (int i = tid; i < 64 * 128; i += 256) {
        int vv = i >> 7, nn = i & 127;
        vs_s[nn * 65 + vv] = __half2float(g_vh[(((size_t)b * 64 + vv) << 10) + nc + nn]);
    }
    __syncthreads();
    float acc[16] = {};
    for (int nn = s * 32; nn < s * 32 + 32; nn++) {
        float vv = vs_s[nn * 65 + v];
        #pragma unroll
        for (int k = 0; k < 16; k++) acc[k] += sm_s[k * 128 + nn] * vv;
    }
    __syncthreads();
    #pragma unroll
    for (int k = 0; k < 16; k++) sbuf[s * 1024 + k * 64 + v] = acc[k];
    __syncthreads();
    for (int e = tid; e < 1024; e += 256)
        g_lcp[part][b * 1024 + e] = sbuf[e] + sbuf[1024 + e] + sbuf[2048 + e] + sbuf[3072 + e];
}

// ---------------- K5: lambda_p GEMM (round-10 structure, reverted) ------------
// grid (8 ntb, 8 bvt, 8 kg), 256 threads, 3-stage single-thread bulk pipeline.
#define GEMM_SMEM (1024 + 3 * 65536)

__global__ __launch_bounds__(256) void k_gemm(const float* __restrict__ emb)
{
#if USE_TC
    extern __shared__ char dsm[];
    __shared__ __align__(16) uint64_t s_full[3], s_mma[3];
    __shared__ uint32_t s_tmem;

    int tid = threadIdx.x;
    int wid = tid >> 5, lane = tid & 31;
    int kg = blockIdx.z;
    int ntb = blockIdx.x;
    int bvt = blockIdx.y;
    int n0 = ntb * 128;
    int bv0 = bvt * 256;

    int y0 = ntb * 4;
    int c_lo = (y0 > 11) ? ((y0 - 11) >> 1) : 0;
    int c_hi = min(15, (y0 + 14) >> 1);
    int nch = c_hi - c_lo + 1;     // 8..14

    uint32_t raw = smem_u32(dsm);
    uint32_t abase = (raw + 1023) & ~1023u;

    if (wid == 0) { TC_ALLOC(smem_u32(&s_tmem), 512); TC_RELINQ(); }
    if (tid == 0) {
        #pragma unroll
        for (int s = 0; s < 3; s++) { MBAR_INIT(smem_u32(&s_full[s]), 1); MBAR_INIT(smem_u32(&s_mma[s]), 1); }
    }
    __syncthreads();
    uint32_t tmem = s_tmem;

    const uint32_t idesc = (1u << 4) | (32u << 17) | (8u << 24);  // F32 acc, f16, N=256, M=128

    if (tid == 0) {
        const char* Tb = (const char*)g_T;
        const char* Vb = (const char*)g_vhs;
        int fph[3] = {0, 0, 0}, mph[3] = {0, 0, 0};

        #define GEMM_LOAD(ch, s) do {                                                     \
            uint32_t _fb = smem_u32(&s_full[s]);                                          \
            uint32_t _sb = abase + (s) * 65536;                                           \
            MBAR_EXPECT_TX(_fb, 65536u);                                                  \
            bulkcp(_sb,          Tb + (((size_t)(2 * kg)     * 16 + (ch)) * 8 + ntb) * 16384, 16384, _fb); \
            bulkcp(_sb + 16384,  Tb + (((size_t)(2 * kg + 1) * 16 + (ch)) * 8 + ntb) * 16384, 16384, _fb); \
            bulkcp(_sb + 32768,  Vb + (((size_t)(ch) * 8 + bvt) * 32768), 32768, _fb);    \
        } while (0)

        GEMM_LOAD(c_lo + 0, 0);
        GEMM_LOAD(c_lo + 1, 1);
        GEMM_LOAD(c_lo + 2, 2);

        for (int ci = 0; ci < nch; ci++) {
            int s = ci - (ci / 3) * 3;
            MBAR_WAIT(smem_u32(&s_full[s]), fph[s]); fph[s] ^= 1;
            uint32_t sb = abase + s * 65536;
            uint64_t a0 = mk_desc(sb);
            uint64_t a1 = mk_desc(sb + 16384);
            uint64_t bd = mk_desc(sb + 32768);
            #pragma unroll
            for (int ks = 0; ks < 4; ks++) {
                uint32_t en = (ci | ks) != 0;
                mma_f16_ss(tmem,       a0 + ks * 2, bd + ks * 2, idesc, en);
                mma_f16_ss(tmem + 256, a1 + ks * 2, bd + ks * 2, idesc, en);
            }
            TC_COMMIT(smem_u32(&s_mma[s]));
            if (ci + 3 < nch) {
                MBAR_WAIT(smem_u32(&s_mma[s]), mph[s]); mph[s] ^= 1;   // stage smem free
                GEMM_LOAD(c_lo + ci + 3, s);
            }
        }
        MBAR_WAIT(smem_u32(&s_mma[0]), mph[0]);
        MBAR_WAIT(smem_u32(&s_mma[1]), mph[1]);
        MBAR_WAIT(smem_u32(&s_mma[2]), mph[2]);
        #undef GEMM_LOAD
    }
    __syncthreads();
    TC_FENCE_AFTER();

    // epilogue: two D tiles (128n x 256bv fp32) -> g_lph fp16 [b][k][n][v]
    int t = wid >> 2;
    int kk = 2 * kg + t;
    int n_g = n0 + (wid & 3) * 32 + lane;
    for (int c0 = 0; c0 < 256; c0 += 32) {
        uint32_t r[32];
        TC_LD_X32(r, tmem + t * 256 + c0);
        TC_WAIT_LD();
        int bvb = bv0 + c0;
        int b = bvb >> 6, vb = bvb & 63;
        uint32_t h2[16];
        #pragma unroll
        for (int j = 0; j < 16; j++) {
            __half2 h = __floats2half2_rn(__uint_as_float(r[2 * j]), __uint_as_float(r[2 * j + 1]));
            h2[j] = *reinterpret_cast<uint32_t*>(&h);
        }
        __half* dst = g_lph + ((((size_t)(b * 16 + kk) << 10) + n_g) << 6) + vb;
        uint4* d4 = reinterpret_cast<uint4*>(dst);
        #pragma unroll
        for (int q4 = 0; q4 < 4; q4++)
            d4[q4] = make_uint4(h2[4 * q4], h2[4 * q4 + 1], h2[4 * q4 + 2], h2[4 * q4 + 3]);
    }
    __syncthreads();
    if (tid == 0) {
        #pragma unroll
        for (int s = 0; s < 3; s++) { MBAR_INVAL(smem_u32(&s_full[s])); MBAR_INVAL(smem_u32(&s_mma[s])); }
    }
    __syncthreads();
    if (wid == 0) TC_DEALLOC(tmem, 512);

#else  // ---- fallback: scalar direct conv (compile-only; grid 8x8x8 = 512) ----
    extern __shared__ char dsm[];
    float* img = (float*)dsm;
    float* Es  = img + 54 * 55;
    int tid = threadIdx.x;
    int bid = blockIdx.x + blockIdx.y * 8 + blockIdx.z * 64;

    for (int i = tid; i < 16 * 529; i += 256) Es[i] = emb[i];

    for (int pair = 0; pair < 4; pair++) {
        int bv = bid * 4 + pair;
        int b = bv >> 6, v = bv & 63;
        __syncthreads();
        for (int i = tid; i < 54 * 55; i += 256) img[i] = 0.f;
        __syncthreads();
        float vsc = g_vs[v], vsh = g_vb[v];
        const float* src = g_v + ((size_t)bv << 10);
        for (int i = tid; i < 1024; i += 256) {
            int y = i >> 5, x = i & 31;
            img[(y + PADL) * 55 + x + PADL] = src[i] * vsc + vsh;
        }
        __syncthreads();

        for (int it = 0; it < 4; it++) {
            int task = tid + 256 * it;
            int k = task >> 6;
            int rh = task & 63;
            int row = rh >> 1;
            int xb = (rh & 1) << 4;
            float acc[16] = {};
            const float* ek = Es + k * 529;
            #pragma unroll 1
            for (int i = 0; i < RR; i++) {
                const float* rp = img + (row + i) * 55 + xb;
                float r[38];
                #pragma unroll
                for (int tt = 0; tt < 38; tt++) r[tt] = rp[tt];
                const float* ept = ek + i * RR;
                #pragma unroll
                for (int j = 0; j < RR; j++) {
                    float e = ept[j];
                    #pragma unroll
                    for (int x = 0; x < 16; x++) acc[x] += e * r[j + x];
                }
            }
            int nbase = row * 32 + xb;
            __half* o = g_lph + ((((size_t)(b * 16 + k) << 10) + nbase) << 6) + v;
            #pragma unroll
            for (int x = 0; x < 16; x++) o[(size_t)x << 6] = __float2half(acc[x]);
        }
    }
#endif
}

// ---------------- K6: final contraction (fp16 q, lambda_c reduce fused) -------
__global__ __launch_bounds__(256) void k_final(const float* __restrict__ gamma,
                                               float* __restrict__ out)
{
    int b = blockIdx.z;
    int v0 = blockIdx.y * 16;
    int n = blockIdx.x * 256 + threadIdx.x;
    __shared__ float lc_s[256];
    for (int i = threadIdx.x; i < 256; i += 256) {
        int idx = b * 1024 + (i >> 4) * 64 + v0 + (i & 15);
        float sum = 0.f;
        #pragma unroll
        for (int p = 0; p < 8; p++) sum += g_lcp[p][idx];
        lc_s[i] = sum;
    }
    __syncthreads();
    float qv[64];
    #pragma unroll
    for (int ch = 0; ch < 64; ch++)
        qv[ch] = __half2float(g_qh[(((size_t)b * 64 + ch) << 10) + n]);
    float gm = 1.f + gamma[0];
    float y[4][16] = {};
    for (int k = 0; k < 16; k++) {
        const __half2* lp = reinterpret_cast<const __half2*>(
            g_lph + ((((size_t)(b * 16 + k) << 10) + n) << 6) + v0);
        float lam[16];
        #pragma unroll
        for (int j = 0; j < 8; j++) {
            float2 f = __half22float2(lp[j]);
            lam[2 * j] = f.x; lam[2 * j + 1] = f.y;
        }
        #pragma unroll
        for (int jj = 0; jj < 16; jj++) lam[jj] += lc_s[k * 16 + jj];
        #pragma unroll
        for (int h = 0; h < 4; h++) {
            float qh = qv[h * 16 + k];
            #pragma unroll
            for (int jj = 0; jj < 16; jj++) y[h][jj] += qh * lam[jj];
        }
    }
    #pragma unroll
    for (int h = 0; h < 4; h++)
        #pragma unroll
        for (int jj = 0; jj < 16; jj++)
            out[(((size_t)b * 256) + h * 64 + v0 + jj) * NN + n] = y[h][jj] * gm;
}

// ---------------- launch ----------------
extern "C" void kernel_launch(void* const* d_in, const int* in_sizes, int n_in,
                              void* d_out, int out_size)
{
    const float* x      = (const float*)d_in[0];
    const float* Wq     = (const float*)d_in[1];
    const float* bn_q_w = (const float*)d_in[2];
    const float* bn_q_b = (const float*)d_in[3];
    const float* Wk     = (const float*)d_in[4];
    const float* Wv     = (const float*)d_in[5];
    const float* bn_v_w = (const float*)d_in[6];
    const float* bn_v_b = (const float*)d_in[7];
    const float* emb    = (const float*)d_in[8];
    const float* gamma  = (const float*)d_in[9];
    float* out = (float*)d_out;

    cudaFuncSetAttribute(k_gemm, cudaFuncAttributeMaxDynamicSharedMemorySize, GEMM_SMEM);
    cudaFuncSetAttribute(k_proj, cudaFuncAttributeMaxDynamicSharedMemorySize, PROJ_SMEM);

    k_prep<<<34976, 256>>>(x, Wq, Wk, Wv, emb);              // 1
    k_proj<<<dim3(4, 32), 256, PROJ_SMEM>>>();               // 2
    k_stats<<<192, 256>>>(bn_q_w, bn_q_b, bn_v_w, bn_v_b);   // 3
    k_gemm<<<dim3(8, 8, 8), 256, GEMM_SMEM>>>(emb);          // 4  <-- profiled slot
    k_lambdac<<<dim3(32, 8), 256>>>();                       // 5
    k_final<<<dim3(4, 4, 32), 256>>>(gamma, out);            // 6
}

// round 13
// speedup vs baseline: 1.3168x; 1.2630x over previous
#include <cuda_runtime.h>
#include <cuda_fp16.h>
#include <cstdint>
#include <math.h>

#define BB 32
#define CC 256
#define NN 1024
#define QCH 64
#define KCH 16
#define VCH 64
#define HEADS 4
#define KD 16
#define RR 23
#define PADL 11
#define EPSB 1e-5f

#if defined(__CUDA_ARCH_FEAT_SM103_ALL) || defined(__CUDA_ARCH_FEAT_SM100_ALL) || \
    defined(__CUDA_ARCH_FEAT_SM101_ALL) || defined(__CUDA_ARCH_SPECIFIC__) || \
    defined(__CUDA_ARCH_FAMILY_SPECIFIC__)
#define USE_TC 1
#else
#define USE_TC 0
#endif

// ---------------- scratch ----------------
__device__ float g_q[BB * QCH * NN];
__device__ float g_k[BB * KCH * NN];                   // raw (pre-softmax) k
__device__ float g_v[BB * VCH * NN];
__device__ __half g_qh[BB * QCH * NN];                 // BN'd q fp16 [b][ch][n]
__device__ __half g_lph[(size_t)BB * KD * NN * VCH];   // lambda_p fp16 [b][k][n][v]
__device__ float g_lcp[8][BB * KD * VCH];
__device__ float g_qs[QCH], g_qb[QCH];
__device__ float g_vs[VCH], g_vb[VCH];
__device__ float g_smx[BB * KD], g_smi[BB * KD];
// tiled + pre-swizzled operands (SW128 within each tile):
__device__ __align__(1024) __half g_T[(size_t)16 * 1024 * 1024];   // [k16][ch16][nt8] 16KB tiles
__device__ __align__(1024) __half g_vhs[(size_t)2048 * 1024];      // [ch16][bvt8] 32KB tiles
__device__ __half g_vh[(size_t)2048 * 1024];                       // linear for k_lambdac
__device__ __align__(1024) __half g_xh[(size_t)BB * NN * CC];      // [b][ch4][nt8] 16KB tiles
__device__ __align__(1024) __half g_wh[4 * 160 * 64];              // [ch4] 20KB tiles

// ---------------- PTX helpers ----------------
__device__ __forceinline__ uint32_t smem_u32(const void* p) {
    uint32_t r;
    asm("{ .reg .u64 t; cvta.to.shared.u64 t, %1; cvt.u32.u64 %0, t; }" : "=r"(r) : "l"(p));
    return r;
}
__device__ __forceinline__ void bulkcp(uint32_t dst, const void* src, uint32_t bytes, uint32_t mbar) {
    asm volatile("cp.async.bulk.shared::cluster.global.mbarrier::complete_tx::bytes [%0], [%1], %2, [%3];"
        :: "r"(dst), "l"(src), "r"(bytes), "r"(mbar) : "memory");
}
#define MBAR_INIT(a, c) asm volatile("mbarrier.init.shared.b64 [%0], %1;" :: "r"(a), "r"(c) : "memory")
#define MBAR_INVAL(a)   asm volatile("mbarrier.inval.shared.b64 [%0];" :: "r"(a) : "memory")
#define MBAR_EXPECT_TX(a, n) asm volatile("mbarrier.arrive.expect_tx.shared.b64 _, [%0], %1;" :: "r"(a), "r"(n) : "memory")
#define MBAR_WAIT(a, ph) do { \
    uint32_t _m = (a), _p = (ph), _d; \
    asm volatile("{ .reg .pred p; mbarrier.try_wait.parity.acquire.cta.shared::cta.b64 p, [%1], %2; selp.b32 %0,1,0,p; }" \
        : "=r"(_d) : "r"(_m), "r"(_p) : "memory"); \
    if (!_d) { \
        asm volatile("{ .reg .pred P1; WL_%=: mbarrier.try_wait.parity.acquire.cta.shared::cta.b64 P1, [%0], %1, 0x989680; @P1 bra.uni WD_%=; bra.uni WL_%=; WD_%=: }" \
            :: "r"(_m), "r"(_p) : "memory"); \
    } } while (0)

#if USE_TC
#define TC_ALLOC(sa, n)   asm volatile("tcgen05.alloc.cta_group::1.sync.aligned.shared::cta.b32 [%0], %1;" :: "r"(sa), "r"(n) : "memory")
#define TC_DEALLOC(t, n)  asm volatile("tcgen05.dealloc.cta_group::1.sync.aligned.b32 %0, %1;" :: "r"(t), "r"(n))
#define TC_RELINQ()       asm volatile("tcgen05.relinquish_alloc_permit.cta_group::1.sync.aligned;")
#define TC_COMMIT(mb)     asm volatile("tcgen05.commit.cta_group::1.mbarrier::arrive::one.shared::cluster.b64 [%0];" :: "r"(mb) : "memory")
#define TC_FENCE_AFTER()  asm volatile("tcgen05.fence::after_thread_sync;" ::: "memory")
#define TC_WAIT_LD()      asm volatile("tcgen05.wait::ld.sync.aligned;" ::: "memory")

#define TC_LD_X32(r, t) \
    asm volatile("tcgen05.ld.sync.aligned.32x32b.x32.b32 " \
        "{%0,%1,%2,%3,%4,%5,%6,%7,%8,%9,%10,%11,%12,%13,%14,%15," \
        "%16,%17,%18,%19,%20,%21,%22,%23,%24,%25,%26,%27,%28,%29,%30,%31}, [%32];" \
        : "=r"((r)[0]),"=r"((r)[1]),"=r"((r)[2]),"=r"((r)[3]),"=r"((r)[4]),"=r"((r)[5]),"=r"((r)[6]),"=r"((r)[7]), \
          "=r"((r)[8]),"=r"((r)[9]),"=r"((r)[10]),"=r"((r)[11]),"=r"((r)[12]),"=r"((r)[13]),"=r"((r)[14]),"=r"((r)[15]), \
          "=r"((r)[16]),"=r"((r)[17]),"=r"((r)[18]),"=r"((r)[19]),"=r"((r)[20]),"=r"((r)[21]),"=r"((r)[22]),"=r"((r)[23]), \
          "=r"((r)[24]),"=r"((r)[25]),"=r"((r)[26]),"=r"((r)[27]),"=r"((r)[28]),"=r"((r)[29]),"=r"((r)[30]),"=r"((r)[31]) \
        : "r"(t))

__device__ __forceinline__ void mma_f16_ss(uint32_t d, uint64_t ad, uint64_t bd,
                                           uint32_t idesc, uint32_t en) {
    asm volatile(
        "{ .reg .pred p; setp.ne.u32 p, %4, 0;\n\t"
        "tcgen05.mma.cta_group::1.kind::f16 [%0], %1, %2, %3, {%5,%5,%5,%5}, p;\n\t}"
        :: "r"(d), "l"(ad), "l"(bd), "r"(idesc), "r"(en), "r"(0u) : "memory");
}

static constexpr uint64_t DESC_BASE =
    (uint64_t(2) << 61) | (uint64_t(1) << 46) | (uint64_t(64) << 32) | (uint64_t(1) << 16);
__device__ __forceinline__ uint64_t mk_desc(uint32_t a) {
    return DESC_BASE | ((uint64_t)(a >> 4) & 0x3FFF);
}
#endif // USE_TC

__device__ __forceinline__ uint32_t sw128(uint32_t o) { return o ^ ((o >> 3) & 0x70); }

// ---------------- K0: merged prep (xhalf | whalf | buildT) ----------------
__global__ __launch_bounds__(256) void k_prep(
    const float* __restrict__ x, const float* __restrict__ Wq,
    const float* __restrict__ Wk, const float* __restrict__ Wv,
    const float* __restrict__ emb)
{
    int blk = blockIdx.x;
    int tid = threadIdx.x;
    if (blk < 2048) {
        int nt64 = blk & 15, ct = (blk >> 4) & 3, b = blk >> 6;
        int n0 = nt64 * 64, c0 = ct * 64;
        __shared__ float s[64][65];
        for (int i = tid; i < 64 * 64; i += 256) {
            int c = i >> 6, n = i & 63;
            s[c][n] = x[((size_t)b * 256 + c0 + c) * 1024 + n0 + n];
        }
        __syncthreads();
        int nt = n0 >> 7;
        char* tile = (char*)g_xh + (((size_t)b * 4 + ct) * 8 + nt) * 16384;
        for (int i = tid; i < 64 * 32; i += 256) {
            int nl64 = i >> 5, c2 = (i & 31) * 2;
            __half2 h = __floats2half2_rn(s[c2][nl64], s[c2 + 1][nl64]);
            int nl = (n0 & 127) + nl64;
            uint32_t o = sw128(nl * 128 + c2 * 2);
            *reinterpret_cast<__half2*>(tile + o) = h;
        }
    } else if (blk < 2208) {
        int i = (blk - 2048) * 256 + tid;
        int row = i >> 8, c = i & 255;
        float val;
        if (row < 64)       val = Wq[row * 256 + c];
        else if (row < 80)  val = Wk[(row - 64) * 256 + c];
        else if (row < 144) val = Wv[(row - 80) * 256 + c];
        else                val = 0.f;
        int ch = c >> 6, cl = c & 63;
        uint32_t o = sw128(row * 128 + cl * 2);
        *reinterpret_cast<__half*>((char*)g_wh + ch * 20480 + o) = __float2half(val);
    } else {
        size_t i = (size_t)(blk - 2208) * 256 + tid;
        int k = (int)(i >> 19);
        int rem = (int)(i & 0x7FFFF);
        int n = rem >> 9;
        int m0 = (rem & 511) * 2;
        int nt = n >> 7, nl = n & 127;
        int ch = m0 >> 6, ml = m0 & 63;
        {
            int y0t = nt * 4;
            int clo = (y0t > 11) ? ((y0t - 11) >> 1) : 0;
            int chi = min(15, (y0t + 14) >> 1);
            if (ch < clo || ch > chi) return;
        }
        int yn = n >> 5, xn = n & 31;
        float f[2];
        #pragma unroll
        for (int e = 0; e < 2; e++) {
            int mm = m0 + e;
            int dy = (mm >> 5) - yn + 11;
            int dx = (mm & 31) - xn + 11;
            f[e] = ((unsigned)dy < 23u && (unsigned)dx < 23u) ? emb[k * 529 + dy * 23 + dx] : 0.f;
        }
        __half2 h = __floats2half2_rn(f[0], f[1]);
        char* tile = (char*)g_T + (((size_t)k * 16 + ch) * 8 + nt) * 16384;
        *reinterpret_cast<__half2*>(tile + sw128(nl * 128 + ml * 2)) = h;
    }
}

// ---------------- K1: projections via bulk-copy + tcgen05 --------
#define PROJ_SMEM (1024 + 8 * 16384 + 4 * 20480)

__global__ __launch_bounds__(256) void k_proj()
{
#if USE_TC
    extern __shared__ char dsm[];
    __shared__ __align__(16) uint64_t s_full, s_mma;
    __shared__ uint32_t s_tmem;
    int tid = threadIdx.x;
    int wid = tid >> 5, lane = tid & 31;
    int b = blockIdx.y;
    int n0 = blockIdx.x * 256;

    uint32_t raw = smem_u32(dsm);
    uint32_t Ab = (raw + 1023) & ~1023u;
    uint32_t Bb = Ab + 8 * 16384;

    if (wid == 0) { TC_ALLOC(smem_u32(&s_tmem), 512); TC_RELINQ(); }
    if (tid == 0) { MBAR_INIT(smem_u32(&s_full), 1); MBAR_INIT(smem_u32(&s_mma), 1); }
    __syncthreads();
    uint32_t tmem = s_tmem;

    const uint32_t idesc = (1u << 4) | (20u << 17) | (8u << 24);  // F32 acc, f16, N=160, M=128
    if (tid == 0) {
        uint32_t fb = smem_u32(&s_full);
        MBAR_EXPECT_TX(fb, 8u * 16384u + 4u * 20480u);
        #pragma unroll
        for (int t = 0; t < 2; t++)
            #pragma unroll
            for (int c = 0; c < 4; c++)
                bulkcp(Ab + (t * 4 + c) * 16384,
                       (const char*)g_xh + (((size_t)b * 4 + c) * 8 + (blockIdx.x * 2 + t)) * 16384,
                       16384, fb);
        #pragma unroll
        for (int c = 0; c < 4; c++)
            bulkcp(Bb + c * 20480, (const char*)g_wh + c * 20480, 20480, fb);
        MBAR_WAIT(fb, 0);
        #pragma unroll
        for (int c = 0; c < 4; c++)
            #pragma unroll
            for (int t = 0; t < 2; t++) {
                uint64_t ad = mk_desc(Ab + (t * 4 + c) * 16384);
                uint64_t bd = mk_desc(Bb + c * 20480);
                #pragma unroll
                for (int ks = 0; ks < 4; ks++)
                    mma_f16_ss(tmem + t * 160, ad + ks * 2, bd + ks * 2, idesc, (c | ks) != 0);
            }
        TC_COMMIT(smem_u32(&s_mma));
    }
    MBAR_WAIT(smem_u32(&s_mma), 0);
    TC_FENCE_AFTER();

    int t = wid >> 2;
    int n_g = n0 + t * 128 + (wid & 3) * 32 + lane;
    for (int c0 = 0; c0 < 160; c0 += 32) {
        uint32_t r[32];
        TC_LD_X32(r, tmem + t * 160 + c0);
        TC_WAIT_LD();
        #pragma unroll
        for (int j = 0; j < 32; j++) {
            int ch = c0 + j;
            float val = __uint_as_float(r[j]);
            if (ch < 64)       g_q[(((size_t)b * 64 + ch) << 10) + n_g] = val;
            else if (ch < 80)  g_k[(((size_t)b * 16 + (ch - 64)) << 10) + n_g] = val;
            else if (ch < 144) g_v[(((size_t)b * 64 + (ch - 80)) << 10) + n_g] = val;
        }
    }
    __syncthreads();
    if (tid == 0) { MBAR_INVAL(smem_u32(&s_full)); MBAR_INVAL(smem_u32(&s_mma)); }
    __syncthreads();
    if (wid == 0) TC_DEALLOC(tmem, 512);
#else
    int b = blockIdx.y;
    int n = blockIdx.x * 256 + threadIdx.x;
    int nt = n >> 7, nl = n & 127;
    for (int ch = 0; ch < 144; ch++) {
        float acc = 0.f;
        for (int c = 0; c < 256; c++) {
            int cc = c >> 6, cl = c & 63;
            const char* at = (const char*)g_xh + (((size_t)b * 4 + cc) * 8 + nt) * 16384;
            const char* wt = (const char*)g_wh + cc * 20480;
            float xa = __half2float(*reinterpret_cast<const __half*>(at + sw128(nl * 128 + cl * 2)));
            float wa = __half2float(*reinterpret_cast<const __half*>(wt + sw128(ch * 128 + cl * 2)));
            acc += xa * wa;
        }
        if (ch < 64)       g_q[(((size_t)b * 64 + ch) << 10) + n] = acc;
        else if (ch < 80)  g_k[(((size_t)b * 16 + (ch - 64)) << 10) + n] = acc;
        else               g_v[(((size_t)b * 64 + (ch - 80)) << 10) + n] = acc;
    }
#endif
}

// ---------------- K2: merged stats: BN (0..127) + softmax (128..191) ----------
__global__ __launch_bounds__(256) void k_stats(
    const float* __restrict__ bnw_q, const float* __restrict__ bnb_q,
    const float* __restrict__ bnw_v, const float* __restrict__ bnb_v)
{
    int blk = blockIdx.x;
    int tid = threadIdx.x;
    if (blk < 128) {
        int ch = blk;
        const float* src = (ch < 64) ? (g_q + (size_t)ch * NN) : (g_v + (size_t)(ch - 64) * NN);
        float s = 0.f, s2 = 0.f;
        for (int i = tid; i < BB * NN; i += 256) {
            int b = i >> 10, n = i & 1023;
            float v = src[((size_t)b * 64 << 10) + n];
            s += v; s2 += v * v;
        }
        __shared__ float rs[256], rs2[256];
        __shared__ float s_sc, s_sh;
        rs[tid] = s; rs2[tid] = s2;
        __syncthreads();
        for (int st = 128; st > 0; st >>= 1) {
            if (tid < st) { rs[tid] += rs[tid + st]; rs2[tid] += rs2[tid + st]; }
            __syncthreads();
        }
        if (tid == 0) {
            float inv = 1.f / (float)(BB * NN);
            float mean = rs[0] * inv;
            float var = rs2[0] * inv - mean * mean;
            float w, bsh;
            if (ch < 64) { w = bnw_q[ch]; bsh = bnb_q[ch]; }
            else         { w = bnw_v[ch - 64]; bsh = bnb_v[ch - 64]; }
            float sc = w * rsqrtf(var + EPSB);
            float sh = bsh - mean * sc;
            if (ch < 64) { g_qs[ch] = sc; g_qb[ch] = sh; }
            else         { g_vs[ch - 64] = sc; g_vb[ch - 64] = sh; }
            s_sc = sc; s_sh = sh;
        }
        __syncthreads();
        float sc = s_sc, sh = s_sh;
        if (ch < 64) {
            for (int i = tid; i < BB * NN; i += 256) {
                int b = i >> 10, n = i & 1023;
                float val = src[((size_t)b * 64 << 10) + n] * sc + sh;
                g_qh[(((size_t)(b * 64 + ch)) << 10) + n] = __float2half(val);
            }
        } else {
            int v = ch - 64;
            for (int i = tid; i < BB * NN; i += 256) {
                int b = i >> 10, n = i & 1023;
                float val = src[((size_t)b * 64 << 10) + n] * sc + sh;
                __half hv = __float2half(val);
                int bv = b * 64 + v;
                g_vh[(((size_t)bv) << 10) + n] = hv;
                int mch = n >> 6, ml = n & 63;
                int bvt = bv >> 8, bvl = bv & 255;
                char* tile = (char*)g_vhs + (((size_t)mch * 8 + bvt) * 32768);
                *reinterpret_cast<__half*>(tile + sw128(bvl * 128 + ml * 2)) = hv;
            }
        }
    } else {
        int row = (blk - 128) * 8 + (tid >> 5);
        int lane = tid & 31;
        const float* p = g_k + ((size_t)row << 10);
        float mx = -1e30f;
        for (int i = lane; i < 1024; i += 32) mx = fmaxf(mx, p[i]);
        #pragma unroll
        for (int o = 16; o; o >>= 1) mx = fmaxf(mx, __shfl_xor_sync(~0u, mx, o));
        float sm = 0.f;
        for (int i = lane; i < 1024; i += 32) sm += expf(p[i] - mx);
        #pragma unroll
        for (int o = 16; o; o >>= 1) sm += __shfl_xor_sync(~0u, sm, o);
        if (lane == 0) { g_smx[row] = mx; g_smi[row] = 1.f / sm; }
    }
}

// ---------------- K3: lambda_c partials ----------------
__global__ __launch_bounds__(256) void k_lambdac()
{
    int b = blockIdx.x;
    int part = blockIdx.y;
    int nc = part * 128;
    int tid = threadIdx.x;
    int s = tid >> 6, v = tid & 63;
    __shared__ float sbuf[16 * 128 + 128 * 65];
    __shared__ float s_mx[16], s_mi[16];
    float* sm_s = sbuf;
    float* vs_s = sbuf + 16 * 128;

    if (tid < 16) { s_mx[tid] = g_smx[b * 16 + tid]; s_mi[tid] = g_smi[b * 16 + tid]; }
    __syncthreads();

    for (int i = tid; i < 16 * 128; i += 256) {
        int k = i >> 7, nn = i & 127;
        float raw = g_k[(((size_t)b * 16 + k) << 10) + nc + nn];
        sm_s[k * 128 + nn] = expf(raw - s_mx[k]) * s_mi[k];
    }
    for (int i = tid; i < 64 * 128; i += 256) {
        int vv = i >> 7, nn = i & 127;
        vs_s[nn * 65 + vv] = __half2float(g_vh[(((size_t)b * 64 + vv) << 10) + nc + nn]);
    }
    __syncthreads();
    float acc[16] = {};
    for (int nn = s * 32; nn < s * 32 + 32; nn++) {
        float vv = vs_s[nn * 65 + v];
        #pragma unroll
        for (int k = 0; k < 16; k++) acc[k] += sm_s[k * 128 + nn] * vv;
    }
    __syncthreads();
    #pragma unroll
    for (int k = 0; k < 16; k++) sbuf[s * 1024 + k * 64 + v] = acc[k];
    __syncthreads();
    for (int e = tid; e < 1024; e += 256)
        g_lcp[part][b * 1024 + e] = sbuf[e] + sbuf[1024 + e] + sbuf[2048 + e] + sbuf[3072 + e];
}

// ---------------- K5: lambda_p GEMM (bulk loads + DEFERRED refill) ------------
// grid (8 ntb, 8 bvt, 8 kg), 256 threads, 3-stage pipeline; refill waits on
// MMA(ci-1) (already complete while MMA(ci) runs) -> 2 MMAs in flight.
#define GEMM_SMEM (1024 + 3 * 65536)

__global__ __launch_bounds__(256) void k_gemm(const float* __restrict__ emb)
{
#if USE_TC
    extern __shared__ char dsm[];
    __shared__ __align__(16) uint64_t s_full[3], s_mma[3];
    __shared__ uint32_t s_tmem;

    int tid = threadIdx.x;
    int wid = tid >> 5, lane = tid & 31;
    int kg = blockIdx.z;
    int ntb = blockIdx.x;
    int bvt = blockIdx.y;
    int n0 = ntb * 128;
    int bv0 = bvt * 256;

    int y0 = ntb * 4;
    int c_lo = (y0 > 11) ? ((y0 - 11) >> 1) : 0;
    int c_hi = min(15, (y0 + 14) >> 1);
    int nch = c_hi - c_lo + 1;     // 8..14

    uint32_t raw = smem_u32(dsm);
    uint32_t abase = (raw + 1023) & ~1023u;

    if (wid == 0) { TC_ALLOC(smem_u32(&s_tmem), 512); TC_RELINQ(); }
    if (tid == 0) {
        #pragma unroll
        for (int s = 0; s < 3; s++) { MBAR_INIT(smem_u32(&s_full[s]), 1); MBAR_INIT(smem_u32(&s_mma[s]), 1); }
    }
    __syncthreads();
    uint32_t tmem = s_tmem;

    const uint32_t idesc = (1u << 4) | (32u << 17) | (8u << 24);  // F32 acc, f16, N=256, M=128

    if (tid == 0) {
        const char* Tb = (const char*)g_T;
        const char* Vb = (const char*)g_vhs;
        int fph[3] = {0, 0, 0}, mph[3] = {0, 0, 0};

        #define GEMM_LOAD(ch, s) do {                                                     \
            uint32_t _fb = smem_u32(&s_full[s]);                                          \
            uint32_t _sb = abase + (s) * 65536;                                           \
            MBAR_EXPECT_TX(_fb, 65536u);                                                  \
            bulkcp(_sb,          Tb + (((size_t)(2 * kg)     * 16 + (ch)) * 8 + ntb) * 16384, 16384, _fb); \
            bulkcp(_sb + 16384,  Tb + (((size_t)(2 * kg + 1) * 16 + (ch)) * 8 + ntb) * 16384, 16384, _fb); \
            bulkcp(_sb + 32768,  Vb + (((size_t)(ch) * 8 + bvt) * 32768), 32768, _fb);    \
        } while (0)

        GEMM_LOAD(c_lo + 0, 0);
        GEMM_LOAD(c_lo + 1, 1);
        GEMM_LOAD(c_lo + 2, 2);

        for (int ci = 0; ci < nch; ci++) {
            int s = ci - (ci / 3) * 3;
            MBAR_WAIT(smem_u32(&s_full[s]), fph[s]); fph[s] ^= 1;
            uint32_t sb = abase + s * 65536;
            uint64_t a0 = mk_desc(sb);
            uint64_t a1 = mk_desc(sb + 16384);
            uint64_t bd = mk_desc(sb + 32768);
            #pragma unroll
            for (int ks = 0; ks < 4; ks++) {
                uint32_t en = (ci | ks) != 0;
                mma_f16_ss(tmem,       a0 + ks * 2, bd + ks * 2, idesc, en);
                mma_f16_ss(tmem + 256, a1 + ks * 2, bd + ks * 2, idesc, en);
            }
            TC_COMMIT(smem_u32(&s_mma[s]));
            // DEFERRED refill: MMA(ci-1)'s stage -> chunk ci+2 (= stage (ci+2)%3 = (ci-1)%3)
            if (ci >= 1 && ci + 2 < nch) {
                int sp = (ci - 1) - ((ci - 1) / 3) * 3;
                MBAR_WAIT(smem_u32(&s_mma[sp]), mph[sp]); mph[sp] ^= 1;
                GEMM_LOAD(c_lo + ci + 2, sp);
            }
        }
        // un-waited commits: MMA(nch-3), MMA(nch-2), MMA(nch-1) -> all 3 stages
        MBAR_WAIT(smem_u32(&s_mma[0]), mph[0]);
        MBAR_WAIT(smem_u32(&s_mma[1]), mph[1]);
        MBAR_WAIT(smem_u32(&s_mma[2]), mph[2]);
        #undef GEMM_LOAD
    }
    __syncthreads();
    TC_FENCE_AFTER();

    // epilogue: two D tiles (128n x 256bv fp32) -> g_lph fp16 [b][k][n][v]
    int t = wid >> 2;
    int kk = 2 * kg + t;
    int n_g = n0 + (wid & 3) * 32 + lane;
    for (int c0 = 0; c0 < 256; c0 += 32) {
        uint32_t r[32];
        TC_LD_X32(r, tmem + t * 256 + c0);
        TC_WAIT_LD();
        int bvb = bv0 + c0;
        int b = bvb >> 6, vb = bvb & 63;
        uint32_t h2[16];
        #pragma unroll
        for (int j = 0; j < 16; j++) {
            __half2 h = __floats2half2_rn(__uint_as_float(r[2 * j]), __uint_as_float(r[2 * j + 1]));
            h2[j] = *reinterpret_cast<uint32_t*>(&h);
        }
        __half* dst = g_lph + ((((size_t)(b * 16 + kk) << 10) + n_g) << 6) + vb;
        uint4* d4 = reinterpret_cast<uint4*>(dst);
        #pragma unroll
        for (int q4 = 0; q4 < 4; q4++)
            d4[q4] = make_uint4(h2[4 * q4], h2[4 * q4 + 1], h2[4 * q4 + 2], h2[4 * q4 + 3]);
    }
    __syncthreads();
    if (tid == 0) {
        #pragma unroll
        for (int s = 0; s < 3; s++) { MBAR_INVAL(smem_u32(&s_full[s])); MBAR_INVAL(smem_u32(&s_mma[s])); }
    }
    __syncthreads();
    if (wid == 0) TC_DEALLOC(tmem, 512);

#else  // ---- fallback: scalar direct conv (compile-only; grid 8x8x8 = 512) ----
    extern __shared__ char dsm[];
    float* img = (float*)dsm;
    float* Es  = img + 54 * 55;
    int tid = threadIdx.x;
    int bid = blockIdx.x + blockIdx.y * 8 + blockIdx.z * 64;

    for (int i = tid; i < 16 * 529; i += 256) Es[i] = emb[i];

    for (int pair = 0; pair < 4; pair++) {
        int bv = bid * 4 + pair;
        int b = bv >> 6, v = bv & 63;
        __syncthreads();
        for (int i = tid; i < 54 * 55; i += 256) img[i] = 0.f;
        __syncthreads();
        float vsc = g_vs[v], vsh = g_vb[v];
        const float* src = g_v + ((size_t)bv << 10);
        for (int i = tid; i < 1024; i += 256) {
            int y = i >> 5, x = i & 31;
            img[(y + PADL) * 55 + x + PADL] = src[i] * vsc + vsh;
        }
        __syncthreads();

        for (int it = 0; it < 4; it++) {
            int task = tid + 256 * it;
            int k = task >> 6;
            int rh = task & 63;
            int row = rh >> 1;
            int xb = (rh & 1) << 4;
            float acc[16] = {};
            const float* ek = Es + k * 529;
            #pragma unroll 1
            for (int i = 0; i < RR; i++) {
                const float* rp = img + (row + i) * 55 + xb;
                float r[38];
                #pragma unroll
                for (int tt = 0; tt < 38; tt++) r[tt] = rp[tt];
                const float* ept = ek + i * RR;
                #pragma unroll
                for (int j = 0; j < RR; j++) {
                    float e = ept[j];
                    #pragma unroll
                    for (int x = 0; x < 16; x++) acc[x] += e * r[j + x];
                }
            }
            int nbase = row * 32 + xb;
            __half* o = g_lph + ((((size_t)(b * 16 + k) << 10) + nbase) << 6) + v;
            #pragma unroll
            for (int x = 0; x < 16; x++) o[(size_t)x << 6] = __float2half(acc[x]);
        }
    }
#endif
}

// ---------------- K6: final contraction v2 — coalesced reads AND writes -------
// grid (16 ntile, 32 b), block 256 = (64 n x 4 vgroup). Per-k, a warp reads
// 8n x 128B contiguous lambda lines. Results staged in smem, written coalesced.
#define FINAL_SMEM (256 * 65 * 4 + 64 * 64 * 2 + 16 * 64 * 4)   // y_s | q_s | lc_s

__global__ __launch_bounds__(256) void k_final(const float* __restrict__ gamma,
                                               float* __restrict__ out)
{
    extern __shared__ char fsm[];
    float* y_s  = (float*)fsm;                         // [256 ch][65 pad] fp32
    __half* q_s = (__half*)(fsm + 256 * 65 * 4);       // [64 ch][64 n]
    float* lc_s = (float*)(fsm + 256 * 65 * 4 + 64 * 64 * 2);  // [16 k][64 v]

    int b = blockIdx.y;
    int n0 = blockIdx.x * 64;
    int tid = threadIdx.x;
    int n_loc = tid >> 2;          // 0..63
    int vg = tid & 3;              // 0..3
    int v0 = vg * 16;
    int n = n0 + n_loc;

    // lc: full 16x64, reduced from 8 partials
    for (int i = tid; i < 1024; i += 256) {
        float sum = 0.f;
        #pragma unroll
        for (int p = 0; p < 8; p++) sum += g_lcp[p][b * 1024 + i];
        lc_s[i] = sum;
    }
    // q: [64 ch][64 n] fp16
    for (int i = tid; i < 64 * 32; i += 256) {
        int ch = i >> 5, n2 = (i & 31) * 2;
        *reinterpret_cast<__half2*>(&q_s[ch * 64 + n2]) =
            *reinterpret_cast<const __half2*>(&g_qh[(((size_t)b * 64 + ch) << 10) + n0 + n2]);
    }
    __syncthreads();

    float y[4][16] = {};
    const __half* lpb = g_lph + (((size_t)b * 16) << 16);   // b*16*1024*64
    for (int k = 0; k < 16; k++) {
        // warp-coalesced: lanes (vg, n) cover 8n x 128B lines
        const uint4* lp = reinterpret_cast<const uint4*>(
            lpb + (((size_t)k << 10) + n) * 64 + v0);
        uint4 ra = lp[0], rb = lp[1];
        __half2 h2[8];
        h2[0] = *reinterpret_cast<__half2*>(&ra.x); h2[1] = *reinterpret_cast<__half2*>(&ra.y);
        h2[2] = *reinterpret_cast<__half2*>(&ra.z); h2[3] = *reinterpret_cast<__half2*>(&ra.w);
        h2[4] = *reinterpret_cast<__half2*>(&rb.x); h2[5] = *reinterpret_cast<__half2*>(&rb.y);
        h2[6] = *reinterpret_cast<__half2*>(&rb.z); h2[7] = *reinterpret_cast<__half2*>(&rb.w);
        float lam[16];
        #pragma unroll
        for (int j = 0; j < 8; j++) {
            float2 f = __half22float2(h2[j]);
            lam[2 * j] = f.x; lam[2 * j + 1] = f.y;
        }
        #pragma unroll
        for (int jj = 0; jj < 16; jj++) lam[jj] += lc_s[k * 64 + v0 + jj];
        #pragma unroll
        for (int h = 0; h < 4; h++) {
            float qh = __half2float(q_s[(h * 16 + k) * 64 + n_loc]);
            #pragma unroll
            for (int jj = 0; jj < 16; jj++) y[h][jj] += qh * lam[jj];
        }
    }
    float gm = 1.f + gamma[0];
    #pragma unroll
    for (int h = 0; h < 4; h++)
        #pragma unroll
        for (int jj = 0; jj < 16; jj++)
            y_s[(h * 64 + v0 + jj) * 65 + n_loc] = y[h][jj] * gm;
    __syncthreads();

    // coalesced writeout: 256 ch x 64 n
    for (int it = 0; it < 64; it++) {
        int idx = it * 256 + tid;
        int ch = idx >> 6, nl = idx & 63;
        out[(((size_t)b * 256 + ch) << 10) + n0 + nl] = y_s[ch * 65 + nl];
    }
}

// ---------------- launch ----------------
extern "C" void kernel_launch(void* const* d_in, const int* in_sizes, int n_in,
                              void* d_out, int out_size)
{
    const float* x      = (const float*)d_in[0];
    const float* Wq     = (const float*)d_in[1];
    const float* bn_q_w = (const float*)d_in[2];
    const float* bn_q_b = (const float*)d_in[3];
    const float* Wk     = (const float*)d_in[4];
    const float* Wv     = (const float*)d_in[5];
    const float* bn_v_w = (const float*)d_in[6];
    const float* bn_v_b = (const float*)d_in[7];
    const float* emb    = (const float*)d_in[8];
    const float* gamma  = (const float*)d_in[9];
    float* out = (float*)d_out;

    cudaFuncSetAttribute(k_gemm, cudaFuncAttributeMaxDynamicSharedMemorySize, GEMM_SMEM);
    cudaFuncSetAttribute(k_proj, cudaFuncAttributeMaxDynamicSharedMemorySize, PROJ_SMEM);
    cudaFuncSetAttribute(k_final, cudaFuncAttributeMaxDynamicSharedMemorySize, FINAL_SMEM);

    k_prep<<<34976, 256>>>(x, Wq, Wk, Wv, emb);              // 1
    k_proj<<<dim3(4, 32), 256, PROJ_SMEM>>>();               // 2
    k_stats<<<192, 256>>>(bn_q_w, bn_q_b, bn_v_w, bn_v_b);   // 3
    k_gemm<<<dim3(8, 8, 8), 256, GEMM_SMEM>>>(emb);          // 4  <-- profiled slot
    k_lambdac<<<dim3(32, 8), 256>>>();                       // 5
    k_final<<<dim3(16, 32), 256, FINAL_SMEM>>>(gamma, out);  // 6
}

// round 14
// speedup vs baseline: 1.3376x; 1.0158x over previous
#include <cuda_runtime.h>
#include <cuda_fp16.h>
#include <cstdint>
#include <math.h>

#define BB 32
#define CC 256
#define NN 1024
#define QCH 64
#define KCH 16
#define VCH 64
#define HEADS 4
#define KD 16
#define RR 23
#define PADL 11
#define EPSB 1e-5f

#if defined(__CUDA_ARCH_FEAT_SM103_ALL) || defined(__CUDA_ARCH_FEAT_SM100_ALL) || \
    defined(__CUDA_ARCH_FEAT_SM101_ALL) || defined(__CUDA_ARCH_SPECIFIC__) || \
    defined(__CUDA_ARCH_FAMILY_SPECIFIC__)
#define USE_TC 1
#else
#define USE_TC 0
#endif

// ---------------- scratch ----------------
__device__ float g_q[BB * QCH * NN];
__device__ float g_k[BB * KCH * NN];                   // raw (pre-softmax) k
__device__ float g_v[BB * VCH * NN];
__device__ __half g_qh[BB * QCH * NN];                 // BN'd q fp16 [b][ch][n]
__device__ __half g_lph[(size_t)BB * KD * NN * VCH];   // lambda_p fp16 [b][k][n][v]
__device__ float g_lcp[8][BB * KD * VCH];
__device__ float g_qs[QCH], g_qb[QCH];
__device__ float g_vs[VCH], g_vb[VCH];
__device__ float g_smx[BB * KD], g_smi[BB * KD];
// tiled + pre-swizzled operands (SW128 within each tile):
__device__ __align__(1024) __half g_T[(size_t)16 * 1024 * 1024];   // [k16][ch16][nt8] 16KB tiles
__device__ __align__(1024) __half g_vhs[(size_t)2048 * 1024];      // [ch16][bvt8] 32KB tiles
__device__ __half g_vh[(size_t)2048 * 1024];                       // linear for k_lambdac
__device__ __align__(1024) __half g_xh[(size_t)BB * NN * CC];      // [b][ch4][nt8] 16KB tiles
__device__ __align__(1024) __half g_wh[4 * 160 * 64];              // [ch4] 20KB tiles

// ---------------- PTX helpers ----------------
__device__ __forceinline__ uint32_t smem_u32(const void* p) {
    uint32_t r;
    asm("{ .reg .u64 t; cvta.to.shared.u64 t, %1; cvt.u32.u64 %0, t; }" : "=r"(r) : "l"(p));
    return r;
}
__device__ __forceinline__ void bulkcp(uint32_t dst, const void* src, uint32_t bytes, uint32_t mbar) {
    asm volatile("cp.async.bulk.shared::cluster.global.mbarrier::complete_tx::bytes [%0], [%1], %2, [%3];"
        :: "r"(dst), "l"(src), "r"(bytes), "r"(mbar) : "memory");
}
#define MBAR_INIT(a, c) asm volatile("mbarrier.init.shared.b64 [%0], %1;" :: "r"(a), "r"(c) : "memory")
#define MBAR_INVAL(a)   asm volatile("mbarrier.inval.shared.b64 [%0];" :: "r"(a) : "memory")
#define MBAR_EXPECT_TX(a, n) asm volatile("mbarrier.arrive.expect_tx.shared.b64 _, [%0], %1;" :: "r"(a), "r"(n) : "memory")
#define MBAR_WAIT(a, ph) do { \
    uint32_t _m = (a), _p = (ph), _d; \
    asm volatile("{ .reg .pred p; mbarrier.try_wait.parity.acquire.cta.shared::cta.b64 p, [%1], %2; selp.b32 %0,1,0,p; }" \
        : "=r"(_d) : "r"(_m), "r"(_p) : "memory"); \
    if (!_d) { \
        asm volatile("{ .reg .pred P1; WL_%=: mbarrier.try_wait.parity.acquire.cta.shared::cta.b64 P1, [%0], %1, 0x989680; @P1 bra.uni WD_%=; bra.uni WL_%=; WD_%=: }" \
            :: "r"(_m), "r"(_p) : "memory"); \
    } } while (0)

#if USE_TC
#define TC_ALLOC(sa, n)   asm volatile("tcgen05.alloc.cta_group::1.sync.aligned.shared::cta.b32 [%0], %1;" :: "r"(sa), "r"(n) : "memory")
#define TC_DEALLOC(t, n)  asm volatile("tcgen05.dealloc.cta_group::1.sync.aligned.b32 %0, %1;" :: "r"(t), "r"(n))
#define TC_RELINQ()       asm volatile("tcgen05.relinquish_alloc_permit.cta_group::1.sync.aligned;")
#define TC_COMMIT(mb)     asm volatile("tcgen05.commit.cta_group::1.mbarrier::arrive::one.shared::cluster.b64 [%0];" :: "r"(mb) : "memory")
#define TC_FENCE_AFTER()  asm volatile("tcgen05.fence::after_thread_sync;" ::: "memory")
#define TC_WAIT_LD()      asm volatile("tcgen05.wait::ld.sync.aligned;" ::: "memory")

#define TC_LD_X32(r, t) \
    asm volatile("tcgen05.ld.sync.aligned.32x32b.x32.b32 " \
        "{%0,%1,%2,%3,%4,%5,%6,%7,%8,%9,%10,%11,%12,%13,%14,%15," \
        "%16,%17,%18,%19,%20,%21,%22,%23,%24,%25,%26,%27,%28,%29,%30,%31}, [%32];" \
        : "=r"((r)[0]),"=r"((r)[1]),"=r"((r)[2]),"=r"((r)[3]),"=r"((r)[4]),"=r"((r)[5]),"=r"((r)[6]),"=r"((r)[7]), \
          "=r"((r)[8]),"=r"((r)[9]),"=r"((r)[10]),"=r"((r)[11]),"=r"((r)[12]),"=r"((r)[13]),"=r"((r)[14]),"=r"((r)[15]), \
          "=r"((r)[16]),"=r"((r)[17]),"=r"((r)[18]),"=r"((r)[19]),"=r"((r)[20]),"=r"((r)[21]),"=r"((r)[22]),"=r"((r)[23]), \
          "=r"((r)[24]),"=r"((r)[25]),"=r"((r)[26]),"=r"((r)[27]),"=r"((r)[28]),"=r"((r)[29]),"=r"((r)[30]),"=r"((r)[31]) \
        : "r"(t))

__device__ __forceinline__ void mma_f16_ss(uint32_t d, uint64_t ad, uint64_t bd,
                                           uint32_t idesc, uint32_t en) {
    asm volatile(
        "{ .reg .pred p; setp.ne.u32 p, %4, 0;\n\t"
        "tcgen05.mma.cta_group::1.kind::f16 [%0], %1, %2, %3, {%5,%5,%5,%5}, p;\n\t}"
        :: "r"(d), "l"(ad), "l"(bd), "r"(idesc), "r"(en), "r"(0u) : "memory");
}

static constexpr uint64_t DESC_BASE =
    (uint64_t(2) << 61) | (uint64_t(1) << 46) | (uint64_t(64) << 32) | (uint64_t(1) << 16);
__device__ __forceinline__ uint64_t mk_desc(uint32_t a) {
    return DESC_BASE | ((uint64_t)(a >> 4) & 0x3FFF);
}
#endif // USE_TC

__device__ __forceinline__ uint32_t sw128(uint32_t o) { return o ^ ((o >> 3) & 0x70); }

// ---------------- K0a: prep x + W (stream 0) ----------------
__global__ __launch_bounds__(256) void k_prep_x(
    const float* __restrict__ x, const float* __restrict__ Wq,
    const float* __restrict__ Wk, const float* __restrict__ Wv)
{
    int blk = blockIdx.x;
    int tid = threadIdx.x;
    if (blk < 2048) {
        int nt64 = blk & 15, ct = (blk >> 4) & 3, b = blk >> 6;
        int n0 = nt64 * 64, c0 = ct * 64;
        __shared__ float s[64][65];
        for (int i = tid; i < 64 * 64; i += 256) {
            int c = i >> 6, n = i & 63;
            s[c][n] = x[((size_t)b * 256 + c0 + c) * 1024 + n0 + n];
        }
        __syncthreads();
        int nt = n0 >> 7;
        char* tile = (char*)g_xh + (((size_t)b * 4 + ct) * 8 + nt) * 16384;
        for (int i = tid; i < 64 * 32; i += 256) {
            int nl64 = i >> 5, c2 = (i & 31) * 2;
            __half2 h = __floats2half2_rn(s[c2][nl64], s[c2 + 1][nl64]);
            int nl = (n0 & 127) + nl64;
            uint32_t o = sw128(nl * 128 + c2 * 2);
            *reinterpret_cast<__half2*>(tile + o) = h;
        }
    } else {
        int i = (blk - 2048) * 256 + tid;
        int row = i >> 8, c = i & 255;
        float val;
        if (row < 64)       val = Wq[row * 256 + c];
        else if (row < 80)  val = Wk[(row - 64) * 256 + c];
        else if (row < 144) val = Wv[(row - 80) * 256 + c];
        else                val = 0.f;
        int ch = c >> 6, cl = c & 63;
        uint32_t o = sw128(row * 128 + cl * 2);
        *reinterpret_cast<__half*>((char*)g_wh + ch * 20480 + o) = __float2half(val);
    }
}

// ---------------- K0b: buildT (stream 2, overlaps proj/stats) ----------------
__global__ __launch_bounds__(256) void k_prep_T(const float* __restrict__ emb)
{
    size_t i = (size_t)blockIdx.x * 256 + threadIdx.x;
    int k = (int)(i >> 19);
    int rem = (int)(i & 0x7FFFF);
    int n = rem >> 9;
    int m0 = (rem & 511) * 2;
    int nt = n >> 7, nl = n & 127;
    int ch = m0 >> 6, ml = m0 & 63;
    {
        int y0t = nt * 4;
        int clo = (y0t > 11) ? ((y0t - 11) >> 1) : 0;
        int chi = min(15, (y0t + 14) >> 1);
        if (ch < clo || ch > chi) return;
    }
    int yn = n >> 5, xn = n & 31;
    float f[2];
    #pragma unroll
    for (int e = 0; e < 2; e++) {
        int mm = m0 + e;
        int dy = (mm >> 5) - yn + 11;
        int dx = (mm & 31) - xn + 11;
        f[e] = ((unsigned)dy < 23u && (unsigned)dx < 23u) ? emb[k * 529 + dy * 23 + dx] : 0.f;
    }
    __half2 h = __floats2half2_rn(f[0], f[1]);
    char* tile = (char*)g_T + (((size_t)k * 16 + ch) * 8 + nt) * 16384;
    *reinterpret_cast<__half2*>(tile + sw128(nl * 128 + ml * 2)) = h;
}

// ---------------- K1: projections via bulk-copy + tcgen05 --------
#define PROJ_SMEM (1024 + 8 * 16384 + 4 * 20480)

__global__ __launch_bounds__(256) void k_proj()
{
#if USE_TC
    extern __shared__ char dsm[];
    __shared__ __align__(16) uint64_t s_full, s_mma;
    __shared__ uint32_t s_tmem;
    int tid = threadIdx.x;
    int wid = tid >> 5, lane = tid & 31;
    int b = blockIdx.y;
    int n0 = blockIdx.x * 256;

    uint32_t raw = smem_u32(dsm);
    uint32_t Ab = (raw + 1023) & ~1023u;
    uint32_t Bb = Ab + 8 * 16384;

    if (wid == 0) { TC_ALLOC(smem_u32(&s_tmem), 512); TC_RELINQ(); }
    if (tid == 0) { MBAR_INIT(smem_u32(&s_full), 1); MBAR_INIT(smem_u32(&s_mma), 1); }
    __syncthreads();
    uint32_t tmem = s_tmem;

    const uint32_t idesc = (1u << 4) | (20u << 17) | (8u << 24);  // F32 acc, f16, N=160, M=128
    if (tid == 0) {
        uint32_t fb = smem_u32(&s_full);
        MBAR_EXPECT_TX(fb, 8u * 16384u + 4u * 20480u);
        #pragma unroll
        for (int t = 0; t < 2; t++)
            #pragma unroll
            for (int c = 0; c < 4; c++)
                bulkcp(Ab + (t * 4 + c) * 16384,
                       (const char*)g_xh + (((size_t)b * 4 + c) * 8 + (blockIdx.x * 2 + t)) * 16384,
                       16384, fb);
        #pragma unroll
        for (int c = 0; c < 4; c++)
            bulkcp(Bb + c * 20480, (const char*)g_wh + c * 20480, 20480, fb);
        MBAR_WAIT(fb, 0);
        #pragma unroll
        for (int c = 0; c < 4; c++)
            #pragma unroll
            for (int t = 0; t < 2; t++) {
                uint64_t ad = mk_desc(Ab + (t * 4 + c) * 16384);
                uint64_t bd = mk_desc(Bb + c * 20480);
                #pragma unroll
                for (int ks = 0; ks < 4; ks++)
                    mma_f16_ss(tmem + t * 160, ad + ks * 2, bd + ks * 2, idesc, (c | ks) != 0);
            }
        TC_COMMIT(smem_u32(&s_mma));
    }
    MBAR_WAIT(smem_u32(&s_mma), 0);
    TC_FENCE_AFTER();

    int t = wid >> 2;
    int n_g = n0 + t * 128 + (wid & 3) * 32 + lane;
    for (int c0 = 0; c0 < 160; c0 += 32) {
        uint32_t r[32];
        TC_LD_X32(r, tmem + t * 160 + c0);
        TC_WAIT_LD();
        #pragma unroll
        for (int j = 0; j < 32; j++) {
            int ch = c0 + j;
            float val = __uint_as_float(r[j]);
            if (ch < 64)       g_q[(((size_t)b * 64 + ch) << 10) + n_g] = val;
            else if (ch < 80)  g_k[(((size_t)b * 16 + (ch - 64)) << 10) + n_g] = val;
            else if (ch < 144) g_v[(((size_t)b * 64 + (ch - 80)) << 10) + n_g] = val;
        }
    }
    __syncthreads();
    if (tid == 0) { MBAR_INVAL(smem_u32(&s_full)); MBAR_INVAL(smem_u32(&s_mma)); }
    __syncthreads();
    if (wid == 0) TC_DEALLOC(tmem, 512);
#else
    int b = blockIdx.y;
    int n = blockIdx.x * 256 + threadIdx.x;
    int nt = n >> 7, nl = n & 127;
    for (int ch = 0; ch < 144; ch++) {
        float acc = 0.f;
        for (int c = 0; c < 256; c++) {
            int cc = c >> 6, cl = c & 63;
            const char* at = (const char*)g_xh + (((size_t)b * 4 + cc) * 8 + nt) * 16384;
            const char* wt = (const char*)g_wh + cc * 20480;
            float xa = __half2float(*reinterpret_cast<const __half*>(at + sw128(nl * 128 + cl * 2)));
            float wa = __half2float(*reinterpret_cast<const __half*>(wt + sw128(ch * 128 + cl * 2)));
            acc += xa * wa;
        }
        if (ch < 64)       g_q[(((size_t)b * 64 + ch) << 10) + n] = acc;
        else if (ch < 80)  g_k[(((size_t)b * 16 + (ch - 64)) << 10) + n] = acc;
        else               g_v[(((size_t)b * 64 + (ch - 80)) << 10) + n] = acc;
    }
#endif
}

// ---------------- K2: merged stats: BN (0..127) + softmax (128..191) ----------
__global__ __launch_bounds__(256) void k_stats(
    const float* __restrict__ bnw_q, const float* __restrict__ bnb_q,
    const float* __restrict__ bnw_v, const float* __restrict__ bnb_v)
{
    int blk = blockIdx.x;
    int tid = threadIdx.x;
    if (blk < 128) {
        int ch = blk;
        const float* src = (ch < 64) ? (g_q + (size_t)ch * NN) : (g_v + (size_t)(ch - 64) * NN);
        float s = 0.f, s2 = 0.f;
        for (int i = tid; i < BB * NN; i += 256) {
            int b = i >> 10, n = i & 1023;
            float v = src[((size_t)b * 64 << 10) + n];
            s += v; s2 += v * v;
        }
        __shared__ float rs[256], rs2[256];
        __shared__ float s_sc, s_sh;
        rs[tid] = s; rs2[tid] = s2;
        __syncthreads();
        for (int st = 128; st > 0; st >>= 1) {
            if (tid < st) { rs[tid] += rs[tid + st]; rs2[tid] += rs2[tid + st]; }
            __syncthreads();
        }
        if (tid == 0) {
            float inv = 1.f / (float)(BB * NN);
            float mean = rs[0] * inv;
            float var = rs2[0] * inv - mean * mean;
            float w, bsh;
            if (ch < 64) { w = bnw_q[ch]; bsh = bnb_q[ch]; }
            else         { w = bnw_v[ch - 64]; bsh = bnb_v[ch - 64]; }
            float sc = w * rsqrtf(var + EPSB);
            float sh = bsh - mean * sc;
            if (ch < 64) { g_qs[ch] = sc; g_qb[ch] = sh; }
            else         { g_vs[ch - 64] = sc; g_vb[ch - 64] = sh; }
            s_sc = sc; s_sh = sh;
        }
        __syncthreads();
        float sc = s_sc, sh = s_sh;
        if (ch < 64) {
            for (int i = tid; i < BB * NN; i += 256) {
                int b = i >> 10, n = i & 1023;
                float val = src[((size_t)b * 64 << 10) + n] * sc + sh;
                g_qh[(((size_t)(b * 64 + ch)) << 10) + n] = __float2half(val);
            }
        } else {
            int v = ch - 64;
            for (int i = tid; i < BB * NN; i += 256) {
                int b = i >> 10, n = i & 1023;
                float val = src[((size_t)b * 64 << 10) + n] * sc + sh;
                __half hv = __float2half(val);
                int bv = b * 64 + v;
                g_vh[(((size_t)bv) << 10) + n] = hv;
                int mch = n >> 6, ml = n & 63;
                int bvt = bv >> 8, bvl = bv & 255;
                char* tile = (char*)g_vhs + (((size_t)mch * 8 + bvt) * 32768);
                *reinterpret_cast<__half*>(tile + sw128(bvl * 128 + ml * 2)) = hv;
            }
        }
    } else {
        int row = (blk - 128) * 8 + (tid >> 5);
        int lane = tid & 31;
        const float* p = g_k + ((size_t)row << 10);
        float mx = -1e30f;
        for (int i = lane; i < 1024; i += 32) mx = fmaxf(mx, p[i]);
        #pragma unroll
        for (int o = 16; o; o >>= 1) mx = fmaxf(mx, __shfl_xor_sync(~0u, mx, o));
        float sm = 0.f;
        for (int i = lane; i < 1024; i += 32) sm += expf(p[i] - mx);
        #pragma unroll
        for (int o = 16; o; o >>= 1) sm += __shfl_xor_sync(~0u, sm, o);
        if (lane == 0) { g_smx[row] = mx; g_smi[row] = 1.f / sm; }
    }
}

// ---------------- K3: lambda_c partials (stream 2, overlaps gemm) -------------
__global__ __launch_bounds__(256) void k_lambdac()
{
    int b = blockIdx.x;
    int part = blockIdx.y;
    int nc = part * 128;
    int tid = threadIdx.x;
    int s = tid >> 6, v = tid & 63;
    __shared__ float sbuf[16 * 128 + 128 * 65];
    __shared__ float s_mx[16], s_mi[16];
    float* sm_s = sbuf;
    float* vs_s = sbuf + 16 * 128;

    if (tid < 16) { s_mx[tid] = g_smx[b * 16 + tid]; s_mi[tid] = g_smi[b * 16 + tid]; }
    __syncthreads();

    for (int i = tid; i < 16 * 128; i += 256) {
        int k = i >> 7, nn = i & 127;
        float raw = g_k[(((size_t)b * 16 + k) << 10) + nc + nn];
        sm_s[k * 128 + nn] = expf(raw - s_mx[k]) * s_mi[k];
    }
    for (int i = tid; i < 64 * 128; i += 256) {
        int vv = i >> 7, nn = i & 127;
        vs_s[nn * 65 + vv] = __half2float(g_vh[(((size_t)b * 64 + vv) << 10) + nc + nn]);
    }
    __syncthreads();
    float acc[16] = {};
    for (int nn = s * 32; nn < s * 32 + 32; nn++) {
        float vv = vs_s[nn * 65 + v];
        #pragma unroll
        for (int k = 0; k < 16; k++) acc[k] += sm_s[k * 128 + nn] * vv;
    }
    __syncthreads();
    #pragma unroll
    for (int k = 0; k < 16; k++) sbuf[s * 1024 + k * 64 + v] = acc[k];
    __syncthreads();
    for (int e = tid; e < 1024; e += 256)
        g_lcp[part][b * 1024 + e] = sbuf[e] + sbuf[1024 + e] + sbuf[2048 + e] + sbuf[3072 + e];
}

// ---------------- K5: lambda_p GEMM (bulk loads + deferred refill) ------------
#define GEMM_SMEM (1024 + 3 * 65536)

__global__ __launch_bounds__(256) void k_gemm(const float* __restrict__ emb)
{
#if USE_TC
    extern __shared__ char dsm[];
    __shared__ __align__(16) uint64_t s_full[3], s_mma[3];
    __shared__ uint32_t s_tmem;

    int tid = threadIdx.x;
    int wid = tid >> 5, lane = tid & 31;
    int kg = blockIdx.z;
    int ntb = blockIdx.x;
    int bvt = blockIdx.y;
    int n0 = ntb * 128;
    int bv0 = bvt * 256;

    int y0 = ntb * 4;
    int c_lo = (y0 > 11) ? ((y0 - 11) >> 1) : 0;
    int c_hi = min(15, (y0 + 14) >> 1);
    int nch = c_hi - c_lo + 1;     // 8..14

    uint32_t raw = smem_u32(dsm);
    uint32_t abase = (raw + 1023) & ~1023u;

    if (wid == 0) { TC_ALLOC(smem_u32(&s_tmem), 512); TC_RELINQ(); }
    if (tid == 0) {
        #pragma unroll
        for (int s = 0; s < 3; s++) { MBAR_INIT(smem_u32(&s_full[s]), 1); MBAR_INIT(smem_u32(&s_mma[s]), 1); }
    }
    __syncthreads();
    uint32_t tmem = s_tmem;

    const uint32_t idesc = (1u << 4) | (32u << 17) | (8u << 24);  // F32 acc, f16, N=256, M=128

    if (tid == 0) {
        const char* Tb = (const char*)g_T;
        const char* Vb = (const char*)g_vhs;
        int fph[3] = {0, 0, 0}, mph[3] = {0, 0, 0};

        #define GEMM_LOAD(ch, s) do {                                                     \
            uint32_t _fb = smem_u32(&s_full[s]);                                          \
            uint32_t _sb = abase + (s) * 65536;                                           \
            MBAR_EXPECT_TX(_fb, 65536u);                                                  \
            bulkcp(_sb,          Tb + (((size_t)(2 * kg)     * 16 + (ch)) * 8 + ntb) * 16384, 16384, _fb); \
            bulkcp(_sb + 16384,  Tb + (((size_t)(2 * kg + 1) * 16 + (ch)) * 8 + ntb) * 16384, 16384, _fb); \
            bulkcp(_sb + 32768,  Vb + (((size_t)(ch) * 8 + bvt) * 32768), 32768, _fb);    \
        } while (0)

        GEMM_LOAD(c_lo + 0, 0);
        GEMM_LOAD(c_lo + 1, 1);
        GEMM_LOAD(c_lo + 2, 2);

        for (int ci = 0; ci < nch; ci++) {
            int s = ci - (ci / 3) * 3;
            MBAR_WAIT(smem_u32(&s_full[s]), fph[s]); fph[s] ^= 1;
            uint32_t sb = abase + s * 65536;
            uint64_t a0 = mk_desc(sb);
            uint64_t a1 = mk_desc(sb + 16384);
            uint64_t bd = mk_desc(sb + 32768);
            #pragma unroll
            for (int ks = 0; ks < 4; ks++) {
                uint32_t en = (ci | ks) != 0;
                mma_f16_ss(tmem,       a0 + ks * 2, bd + ks * 2, idesc, en);
                mma_f16_ss(tmem + 256, a1 + ks * 2, bd + ks * 2, idesc, en);
            }
            TC_COMMIT(smem_u32(&s_mma[s]));
            // deferred refill: wait MMA(ci-1), reuse its stage for chunk ci+2
            if (ci >= 1 && ci + 2 < nch) {
                int sp = (ci - 1) - ((ci - 1) / 3) * 3;
                MBAR_WAIT(smem_u32(&s_mma[sp]), mph[sp]); mph[sp] ^= 1;
                GEMM_LOAD(c_lo + ci + 2, sp);
            }
        }
        MBAR_WAIT(smem_u32(&s_mma[0]), mph[0]);
        MBAR_WAIT(smem_u32(&s_mma[1]), mph[1]);
        MBAR_WAIT(smem_u32(&s_mma[2]), mph[2]);
        #undef GEMM_LOAD
    }
    __syncthreads();
    TC_FENCE_AFTER();

    // epilogue: two D tiles (128n x 256bv fp32) -> g_lph fp16 [b][k][n][v]
    int t = wid >> 2;
    int kk = 2 * kg + t;
    int n_g = n0 + (wid & 3) * 32 + lane;
    for (int c0 = 0; c0 < 256; c0 += 32) {
        uint32_t r[32];
        TC_LD_X32(r, tmem + t * 256 + c0);
        TC_WAIT_LD();
        int bvb = bv0 + c0;
        int b = bvb >> 6, vb = bvb & 63;
        uint32_t h2[16];
        #pragma unroll
        for (int j = 0; j < 16; j++) {
            __half2 h = __floats2half2_rn(__uint_as_float(r[2 * j]), __uint_as_float(r[2 * j + 1]));
            h2[j] = *reinterpret_cast<uint32_t*>(&h);
        }
        __half* dst = g_lph + ((((size_t)(b * 16 + kk) << 10) + n_g) << 6) + vb;
        uint4* d4 = reinterpret_cast<uint4*>(dst);
        #pragma unroll
        for (int q4 = 0; q4 < 4; q4++)
            d4[q4] = make_uint4(h2[4 * q4], h2[4 * q4 + 1], h2[4 * q4 + 2], h2[4 * q4 + 3]);
    }
    __syncthreads();
    if (tid == 0) {
        #pragma unroll
        for (int s = 0; s < 3; s++) { MBAR_INVAL(smem_u32(&s_full[s])); MBAR_INVAL(smem_u32(&s_mma[s])); }
    }
    __syncthreads();
    if (wid == 0) TC_DEALLOC(tmem, 512);

#else  // ---- fallback: scalar direct conv (compile-only; grid 8x8x8 = 512) ----
    extern __shared__ char dsm[];
    float* img = (float*)dsm;
    float* Es  = img + 54 * 55;
    int tid = threadIdx.x;
    int bid = blockIdx.x + blockIdx.y * 8 + blockIdx.z * 64;

    for (int i = tid; i < 16 * 529; i += 256) Es[i] = emb[i];

    for (int pair = 0; pair < 4; pair++) {
        int bv = bid * 4 + pair;
        int b = bv >> 6, v = bv & 63;
        __syncthreads();
        for (int i = tid; i < 54 * 55; i += 256) img[i] = 0.f;
        __syncthreads();
        float vsc = g_vs[v], vsh = g_vb[v];
        const float* src = g_v + ((size_t)bv << 10);
        for (int i = tid; i < 1024; i += 256) {
            int y = i >> 5, x = i & 31;
            img[(y + PADL) * 55 + x + PADL] = src[i] * vsc + vsh;
        }
        __syncthreads();

        for (int it = 0; it < 4; it++) {
            int task = tid + 256 * it;
            int k = task >> 6;
            int rh = task & 63;
            int row = rh >> 1;
            int xb = (rh & 1) << 4;
            float acc[16] = {};
            const float* ek = Es + k * 529;
            #pragma unroll 1
            for (int i = 0; i < RR; i++) {
                const float* rp = img + (row + i) * 55 + xb;
                float r[38];
                #pragma unroll
                for (int tt = 0; tt < 38; tt++) r[tt] = rp[tt];
                const float* ept = ek + i * RR;
                #pragma unroll
                for (int j = 0; j < RR; j++) {
                    float e = ept[j];
                    #pragma unroll
                    for (int x = 0; x < 16; x++) acc[x] += e * r[j + x];
                }
            }
            int nbase = row * 32 + xb;
            __half* o = g_lph + ((((size_t)(b * 16 + k) << 10) + nbase) << 6) + v;
            #pragma unroll
            for (int x = 0; x < 16; x++) o[(size_t)x << 6] = __float2half(acc[x]);
        }
    }
#endif
}

// ---------------- K6: final contraction (coalesced reads AND writes) ----------
#define FINAL_SMEM (256 * 65 * 4 + 64 * 64 * 2 + 16 * 64 * 4)   // y_s | q_s | lc_s

__global__ __launch_bounds__(256) void k_final(const float* __restrict__ gamma,
                                               float* __restrict__ out)
{
    extern __shared__ char fsm[];
    float* y_s  = (float*)fsm;                         // [256 ch][65 pad] fp32
    __half* q_s = (__half*)(fsm + 256 * 65 * 4);       // [64 ch][64 n]
    float* lc_s = (float*)(fsm + 256 * 65 * 4 + 64 * 64 * 2);  // [16 k][64 v]

    int b = blockIdx.y;
    int n0 = blockIdx.x * 64;
    int tid = threadIdx.x;
    int n_loc = tid >> 2;
    int vg = tid & 3;
    int v0 = vg * 16;
    int n = n0 + n_loc;

    for (int i = tid; i < 1024; i += 256) {
        float sum = 0.f;
        #pragma unroll
        for (int p = 0; p < 8; p++) sum += g_lcp[p][b * 1024 + i];
        lc_s[i] = sum;
    }
    for (int i = tid; i < 64 * 32; i += 256) {
        int ch = i >> 5, n2 = (i & 31) * 2;
        *reinterpret_cast<__half2*>(&q_s[ch * 64 + n2]) =
            *reinterpret_cast<const __half2*>(&g_qh[(((size_t)b * 64 + ch) << 10) + n0 + n2]);
    }
    __syncthreads();

    float y[4][16] = {};
    const __half* lpb = g_lph + (((size_t)b * 16) << 16);
    for (int k = 0; k < 16; k++) {
        const uint4* lp = reinterpret_cast<const uint4*>(
            lpb + (((size_t)k << 10) + n) * 64 + v0);
        uint4 ra = lp[0], rb = lp[1];
        __half2 h2[8];
        h2[0] = *reinterpret_cast<__half2*>(&ra.x); h2[1] = *reinterpret_cast<__half2*>(&ra.y);
        h2[2] = *reinterpret_cast<__half2*>(&ra.z); h2[3] = *reinterpret_cast<__half2*>(&ra.w);
        h2[4] = *reinterpret_cast<__half2*>(&rb.x); h2[5] = *reinterpret_cast<__half2*>(&rb.y);
        h2[6] = *reinterpret_cast<__half2*>(&rb.z); h2[7] = *reinterpret_cast<__half2*>(&rb.w);
        float lam[16];
        #pragma unroll
        for (int j = 0; j < 8; j++) {
            float2 f = __half22float2(h2[j]);
            lam[2 * j] = f.x; lam[2 * j + 1] = f.y;
        }
        #pragma unroll
        for (int jj = 0; jj < 16; jj++) lam[jj] += lc_s[k * 64 + v0 + jj];
        #pragma unroll
        for (int h = 0; h < 4; h++) {
            float qh = __half2float(q_s[(h * 16 + k) * 64 + n_loc]);
            #pragma unroll
            for (int jj = 0; jj < 16; jj++) y[h][jj] += qh * lam[jj];
        }
    }
    float gm = 1.f + gamma[0];
    #pragma unroll
    for (int h = 0; h < 4; h++)
        #pragma unroll
        for (int jj = 0; jj < 16; jj++)
            y_s[(h * 64 + v0 + jj) * 65 + n_loc] = y[h][jj] * gm;
    __syncthreads();

    for (int it = 0; it < 64; it++) {
        int idx = it * 256 + tid;
        int ch = idx >> 6, nl = idx & 63;
        out[(((size_t)b * 256 + ch) << 10) + n0 + nl] = y_s[ch * 65 + nl];
    }
}

// ---------------- launch: dual-stream fork/join ----------------
extern "C" void kernel_launch(void* const* d_in, const int* in_sizes, int n_in,
                              void* d_out, int out_size)
{
    const float* x      = (const float*)d_in[0];
    const float* Wq     = (const float*)d_in[1];
    const float* bn_q_w = (const float*)d_in[2];
    const float* bn_q_b = (const float*)d_in[3];
    const float* Wk     = (const float*)d_in[4];
    const float* Wv     = (const float*)d_in[5];
    const float* bn_v_w = (const float*)d_in[6];
    const float* bn_v_b = (const float*)d_in[7];
    const float* emb    = (const float*)d_in[8];
    const float* gamma  = (const float*)d_in[9];
    float* out = (float*)d_out;

    cudaFuncSetAttribute(k_gemm, cudaFuncAttributeMaxDynamicSharedMemorySize, GEMM_SMEM);
    cudaFuncSetAttribute(k_proj, cudaFuncAttributeMaxDynamicSharedMemorySize, PROJ_SMEM);
    cudaFuncSetAttribute(k_final, cudaFuncAttributeMaxDynamicSharedMemorySize, FINAL_SMEM);

    // kernel_launch runs only for correctness + one capture; created handles are
    // intentionally not destroyed (destroying a capturing stream would abort capture).
    cudaStream_t s2;
    cudaStreamCreateWithFlags(&s2, cudaStreamNonBlocking);
    cudaEvent_t e0, eT, eS, eL;
    cudaEventCreateWithFlags(&e0, cudaEventDisableTiming);
    cudaEventCreateWithFlags(&eT, cudaEventDisableTiming);
    cudaEventCreateWithFlags(&eS, cudaEventDisableTiming);
    cudaEventCreateWithFlags(&eL, cudaEventDisableTiming);

    // fork: buildT on s2, overlapping the x-path
    cudaEventRecord(e0, 0);
    cudaStreamWaitEvent(s2, e0, 0);
    k_prep_T<<<32768, 256, 0, s2>>>(emb);
    cudaEventRecord(eT, s2);

    k_prep_x<<<2208, 256>>>(x, Wq, Wk, Wv);
    k_proj<<<dim3(4, 32), 256, PROJ_SMEM>>>();
    k_stats<<<192, 256>>>(bn_q_w, bn_q_b, bn_v_w, bn_v_b);
    cudaEventRecord(eS, 0);

    // fork: lambda_c on s2, overlapping the gemm
    cudaStreamWaitEvent(s2, eS, 0);
    k_lambdac<<<dim3(32, 8), 256, 0, s2>>>();
    cudaEventRecord(eL, s2);

    cudaStreamWaitEvent(0, eT, 0);
    k_gemm<<<dim3(8, 8, 8), 256, GEMM_SMEM>>>(emb);
    cudaStreamWaitEvent(0, eL, 0);
    k_final<<<dim3(16, 32), 256, FINAL_SMEM>>>(gamma, out);
}

// round 15
// speedup vs baseline: 1.5598x; 1.1661x over previous
#include <cuda_runtime.h>
#include <cuda_fp16.h>
#include <cstdint>
#include <math.h>

#define BB 32
#define CC 256
#define NN 1024
#define QCH 64
#define KCH 16
#define VCH 64
#define HEADS 4
#define KD 16
#define RR 23
#define PADL 11
#define EPSB 1e-5f

#if defined(__CUDA_ARCH_FEAT_SM103_ALL) || defined(__CUDA_ARCH_FEAT_SM100_ALL) || \
    defined(__CUDA_ARCH_FEAT_SM101_ALL) || defined(__CUDA_ARCH_SPECIFIC__) || \
    defined(__CUDA_ARCH_FAMILY_SPECIFIC__)
#define USE_TC 1
#else
#define USE_TC 0
#endif

// ---------------- scratch ----------------
__device__ float g_q[BB * QCH * NN];
__device__ float g_k[BB * KCH * NN];                   // raw (pre-softmax) k
__device__ float g_v[BB * VCH * NN];
__device__ __half g_qh[BB * QCH * NN];                 // BN'd q fp16 [b][ch][n]
__device__ __half g_lph[(size_t)BB * KD * NN * VCH];   // lambda_p fp16 [b][k][n][v]
__device__ float g_lcp[8][BB * KD * VCH];
__device__ float g_bnp[128][8][2];                     // BN partial sums [ch][part][s,s2]
__device__ float g_smx[BB * KD], g_smi[BB * KD];
// tiled + pre-swizzled operands (SW128 within each tile):
__device__ __align__(1024) __half g_T[(size_t)16 * 1024 * 1024];   // [k16][ch16][nt8] 16KB tiles
__device__ __align__(1024) __half g_vhs[(size_t)2048 * 1024];      // [ch16][bvt8] 32KB tiles
__device__ __half g_vh[(size_t)2048 * 1024];                       // linear for k_lambdac
__device__ __align__(1024) __half g_xh[(size_t)BB * NN * CC];      // [b][ch4][nt8] 16KB tiles
__device__ __align__(1024) __half g_wh[4 * 160 * 64];              // [ch4] 20KB tiles

// ---------------- PTX helpers ----------------
__device__ __forceinline__ uint32_t smem_u32(const void* p) {
    uint32_t r;
    asm("{ .reg .u64 t; cvta.to.shared.u64 t, %1; cvt.u32.u64 %0, t; }" : "=r"(r) : "l"(p));
    return r;
}
__device__ __forceinline__ void bulkcp(uint32_t dst, const void* src, uint32_t bytes, uint32_t mbar) {
    asm volatile("cp.async.bulk.shared::cluster.global.mbarrier::complete_tx::bytes [%0], [%1], %2, [%3];"
        :: "r"(dst), "l"(src), "r"(bytes), "r"(mbar) : "memory");
}
#define MBAR_INIT(a, c) asm volatile("mbarrier.init.shared.b64 [%0], %1;" :: "r"(a), "r"(c) : "memory")
#define MBAR_INVAL(a)   asm volatile("mbarrier.inval.shared.b64 [%0];" :: "r"(a) : "memory")
#define MBAR_EXPECT_TX(a, n) asm volatile("mbarrier.arrive.expect_tx.shared.b64 _, [%0], %1;" :: "r"(a), "r"(n) : "memory")
#define MBAR_WAIT(a, ph) do { \
    uint32_t _m = (a), _p = (ph), _d; \
    asm volatile("{ .reg .pred p; mbarrier.try_wait.parity.acquire.cta.shared::cta.b64 p, [%1], %2; selp.b32 %0,1,0,p; }" \
        : "=r"(_d) : "r"(_m), "r"(_p) : "memory"); \
    if (!_d) { \
        asm volatile("{ .reg .pred P1; WL_%=: mbarrier.try_wait.parity.acquire.cta.shared::cta.b64 P1, [%0], %1, 0x989680; @P1 bra.uni WD_%=; bra.uni WL_%=; WD_%=: }" \
            :: "r"(_m), "r"(_p) : "memory"); \
    } } while (0)

#if USE_TC
#define TC_ALLOC(sa, n)   asm volatile("tcgen05.alloc.cta_group::1.sync.aligned.shared::cta.b32 [%0], %1;" :: "r"(sa), "r"(n) : "memory")
#define TC_DEALLOC(t, n)  asm volatile("tcgen05.dealloc.cta_group::1.sync.aligned.b32 %0, %1;" :: "r"(t), "r"(n))
#define TC_RELINQ()       asm volatile("tcgen05.relinquish_alloc_permit.cta_group::1.sync.aligned;")
#define TC_COMMIT(mb)     asm volatile("tcgen05.commit.cta_group::1.mbarrier::arrive::one.shared::cluster.b64 [%0];" :: "r"(mb) : "memory")
#define TC_FENCE_AFTER()  asm volatile("tcgen05.fence::after_thread_sync;" ::: "memory")
#define TC_WAIT_LD()      asm volatile("tcgen05.wait::ld.sync.aligned;" ::: "memory")

#define TC_LD_X32(r, t) \
    asm volatile("tcgen05.ld.sync.aligned.32x32b.x32.b32 " \
        "{%0,%1,%2,%3,%4,%5,%6,%7,%8,%9,%10,%11,%12,%13,%14,%15," \
        "%16,%17,%18,%19,%20,%21,%22,%23,%24,%25,%26,%27,%28,%29,%30,%31}, [%32];" \
        : "=r"((r)[0]),"=r"((r)[1]),"=r"((r)[2]),"=r"((r)[3]),"=r"((r)[4]),"=r"((r)[5]),"=r"((r)[6]),"=r"((r)[7]), \
          "=r"((r)[8]),"=r"((r)[9]),"=r"((r)[10]),"=r"((r)[11]),"=r"((r)[12]),"=r"((r)[13]),"=r"((r)[14]),"=r"((r)[15]), \
          "=r"((r)[16]),"=r"((r)[17]),"=r"((r)[18]),"=r"((r)[19]),"=r"((r)[20]),"=r"((r)[21]),"=r"((r)[22]),"=r"((r)[23]), \
          "=r"((r)[24]),"=r"((r)[25]),"=r"((r)[26]),"=r"((r)[27]),"=r"((r)[28]),"=r"((r)[29]),"=r"((r)[30]),"=r"((r)[31]) \
        : "r"(t))

__device__ __forceinline__ void mma_f16_ss(uint32_t d, uint64_t ad, uint64_t bd,
                                           uint32_t idesc, uint32_t en) {
    asm volatile(
        "{ .reg .pred p; setp.ne.u32 p, %4, 0;\n\t"
        "tcgen05.mma.cta_group::1.kind::f16 [%0], %1, %2, %3, {%5,%5,%5,%5}, p;\n\t}"
        :: "r"(d), "l"(ad), "l"(bd), "r"(idesc), "r"(en), "r"(0u) : "memory");
}

static constexpr uint64_t DESC_BASE =
    (uint64_t(2) << 61) | (uint64_t(1) << 46) | (uint64_t(64) << 32) | (uint64_t(1) << 16);
__device__ __forceinline__ uint64_t mk_desc(uint32_t a) {
    return DESC_BASE | ((uint64_t)(a >> 4) & 0x3FFF);
}
#endif // USE_TC

__device__ __forceinline__ uint32_t sw128(uint32_t o) { return o ^ ((o >> 3) & 0x70); }

// ---------------- K0a: prep x + W (stream 0) ----------------
__global__ __launch_bounds__(256) void k_prep_x(
    const float* __restrict__ x, const float* __restrict__ Wq,
    const float* __restrict__ Wk, const float* __restrict__ Wv)
{
    int blk = blockIdx.x;
    int tid = threadIdx.x;
    if (blk < 2048) {
        int nt64 = blk & 15, ct = (blk >> 4) & 3, b = blk >> 6;
        int n0 = nt64 * 64, c0 = ct * 64;
        __shared__ float s[64][65];
        for (int i = tid; i < 64 * 64; i += 256) {
            int c = i >> 6, n = i & 63;
            s[c][n] = x[((size_t)b * 256 + c0 + c) * 1024 + n0 + n];
        }
        __syncthreads();
        int nt = n0 >> 7;
        char* tile = (char*)g_xh + (((size_t)b * 4 + ct) * 8 + nt) * 16384;
        for (int i = tid; i < 64 * 32; i += 256) {
            int nl64 = i >> 5, c2 = (i & 31) * 2;
            __half2 h = __floats2half2_rn(s[c2][nl64], s[c2 + 1][nl64]);
            int nl = (n0 & 127) + nl64;
            uint32_t o = sw128(nl * 128 + c2 * 2);
            *reinterpret_cast<__half2*>(tile + o) = h;
        }
    } else {
        int i = (blk - 2048) * 256 + tid;
        int row = i >> 8, c = i & 255;
        float val;
        if (row < 64)       val = Wq[row * 256 + c];
        else if (row < 80)  val = Wk[(row - 64) * 256 + c];
        else if (row < 144) val = Wv[(row - 80) * 256 + c];
        else                val = 0.f;
        int ch = c >> 6, cl = c & 63;
        uint32_t o = sw128(row * 128 + cl * 2);
        *reinterpret_cast<__half*>((char*)g_wh + ch * 20480 + o) = __float2half(val);
    }
}

// ---------------- K0b: buildT (stream 2) ----------------
__global__ __launch_bounds__(256) void k_prep_T(const float* __restrict__ emb)
{
    size_t i = (size_t)blockIdx.x * 256 + threadIdx.x;
    int k = (int)(i >> 19);
    int rem = (int)(i & 0x7FFFF);
    int n = rem >> 9;
    int m0 = (rem & 511) * 2;
    int nt = n >> 7, nl = n & 127;
    int ch = m0 >> 6, ml = m0 & 63;
    {
        int y0t = nt * 4;
        int clo = (y0t > 11) ? ((y0t - 11) >> 1) : 0;
        int chi = min(15, (y0t + 14) >> 1);
        if (ch < clo || ch > chi) return;
    }
    int yn = n >> 5, xn = n & 31;
    float f[2];
    #pragma unroll
    for (int e = 0; e < 2; e++) {
        int mm = m0 + e;
        int dy = (mm >> 5) - yn + 11;
        int dx = (mm & 31) - xn + 11;
        f[e] = ((unsigned)dy < 23u && (unsigned)dx < 23u) ? emb[k * 529 + dy * 23 + dx] : 0.f;
    }
    __half2 h = __floats2half2_rn(f[0], f[1]);
    char* tile = (char*)g_T + (((size_t)k * 16 + ch) * 8 + nt) * 16384;
    *reinterpret_cast<__half2*>(tile + sw128(nl * 128 + ml * 2)) = h;
}

// ---------------- K1: projections via bulk-copy + tcgen05 --------
#define PROJ_SMEM (1024 + 8 * 16384 + 4 * 20480)

__global__ __launch_bounds__(256) void k_proj()
{
#if USE_TC
    extern __shared__ char dsm[];
    __shared__ __align__(16) uint64_t s_full, s_mma;
    __shared__ uint32_t s_tmem;
    int tid = threadIdx.x;
    int wid = tid >> 5, lane = tid & 31;
    int b = blockIdx.y;
    int n0 = blockIdx.x * 256;

    uint32_t raw = smem_u32(dsm);
    uint32_t Ab = (raw + 1023) & ~1023u;
    uint32_t Bb = Ab + 8 * 16384;

    if (wid == 0) { TC_ALLOC(smem_u32(&s_tmem), 512); TC_RELINQ(); }
    if (tid == 0) { MBAR_INIT(smem_u32(&s_full), 1); MBAR_INIT(smem_u32(&s_mma), 1); }
    __syncthreads();
    uint32_t tmem = s_tmem;

    const uint32_t idesc = (1u << 4) | (20u << 17) | (8u << 24);
    if (tid == 0) {
        uint32_t fb = smem_u32(&s_full);
        MBAR_EXPECT_TX(fb, 8u * 16384u + 4u * 20480u);
        #pragma unroll
        for (int t = 0; t < 2; t++)
            #pragma unroll
            for (int c = 0; c < 4; c++)
                bulkcp(Ab + (t * 4 + c) * 16384,
                       (const char*)g_xh + (((size_t)b * 4 + c) * 8 + (blockIdx.x * 2 + t)) * 16384,
                       16384, fb);
        #pragma unroll
        for (int c = 0; c < 4; c++)
            bulkcp(Bb + c * 20480, (const char*)g_wh + c * 20480, 20480, fb);
        MBAR_WAIT(fb, 0);
        #pragma unroll
        for (int c = 0; c < 4; c++)
            #pragma unroll
            for (int t = 0; t < 2; t++) {
                uint64_t ad = mk_desc(Ab + (t * 4 + c) * 16384);
                uint64_t bd = mk_desc(Bb + c * 20480);
                #pragma unroll
                for (int ks = 0; ks < 4; ks++)
                    mma_f16_ss(tmem + t * 160, ad + ks * 2, bd + ks * 2, idesc, (c | ks) != 0);
            }
        TC_COMMIT(smem_u32(&s_mma));
    }
    MBAR_WAIT(smem_u32(&s_mma), 0);
    TC_FENCE_AFTER();

    int t = wid >> 2;
    int n_g = n0 + t * 128 + (wid & 3) * 32 + lane;
    for (int c0 = 0; c0 < 160; c0 += 32) {
        uint32_t r[32];
        TC_LD_X32(r, tmem + t * 160 + c0);
        TC_WAIT_LD();
        #pragma unroll
        for (int j = 0; j < 32; j++) {
            int ch = c0 + j;
            float val = __uint_as_float(r[j]);
            if (ch < 64)       g_q[(((size_t)b * 64 + ch) << 10) + n_g] = val;
            else if (ch < 80)  g_k[(((size_t)b * 16 + (ch - 64)) << 10) + n_g] = val;
            else if (ch < 144) g_v[(((size_t)b * 64 + (ch - 80)) << 10) + n_g] = val;
        }
    }
    __syncthreads();
    if (tid == 0) { MBAR_INVAL(smem_u32(&s_full)); MBAR_INVAL(smem_u32(&s_mma)); }
    __syncthreads();
    if (wid == 0) TC_DEALLOC(tmem, 512);
#else
    int b = blockIdx.y;
    int n = blockIdx.x * 256 + threadIdx.x;
    int nt = n >> 7, nl = n & 127;
    for (int ch = 0; ch < 144; ch++) {
        float acc = 0.f;
        for (int c = 0; c < 256; c++) {
            int cc = c >> 6, cl = c & 63;
            const char* at = (const char*)g_xh + (((size_t)b * 4 + cc) * 8 + nt) * 16384;
            const char* wt = (const char*)g_wh + cc * 20480;
            float xa = __half2float(*reinterpret_cast<const __half*>(at + sw128(nl * 128 + cl * 2)));
            float wa = __half2float(*reinterpret_cast<const __half*>(wt + sw128(ch * 128 + cl * 2)));
            acc += xa * wa;
        }
        if (ch < 64)       g_q[(((size_t)b * 64 + ch) << 10) + n] = acc;
        else if (ch < 80)  g_k[(((size_t)b * 16 + (ch - 64)) << 10) + n] = acc;
        else               g_v[(((size_t)b * 64 + (ch - 80)) << 10) + n] = acc;
    }
#endif
}

// ---------------- K2a: BN partial sums (0..1023) + softmax stats (1024..1087) --
__global__ __launch_bounds__(256) void k_stats1()
{
    int blk = blockIdx.x;
    int tid = threadIdx.x;
    if (blk < 1024) {
        int ch = blk >> 3, part = blk & 7;
        int b0 = part * 4;
        const float* src = (ch < 64) ? (g_q + (size_t)ch * NN) : (g_v + (size_t)(ch - 64) * NN);
        float s = 0.f, s2 = 0.f;
        #pragma unroll
        for (int bb = 0; bb < 4; bb++) {
            const float4* p = reinterpret_cast<const float4*>(src + ((size_t)((b0 + bb) * 64) << 10));
            float4 v = p[tid];
            s  += v.x + v.y + v.z + v.w;
            s2 += v.x * v.x + v.y * v.y + v.z * v.z + v.w * v.w;
        }
        __shared__ float rs[256], rs2[256];
        rs[tid] = s; rs2[tid] = s2;
        __syncthreads();
        for (int st = 128; st > 0; st >>= 1) {
            if (tid < st) { rs[tid] += rs[tid + st]; rs2[tid] += rs2[tid + st]; }
            __syncthreads();
        }
        if (tid == 0) { g_bnp[ch][part][0] = rs[0]; g_bnp[ch][part][1] = rs2[0]; }
    } else {
        int row = (blk - 1024) * 8 + (tid >> 5);
        int lane = tid & 31;
        const float* p = g_k + ((size_t)row << 10);
        float mx = -1e30f;
        for (int i = lane; i < 1024; i += 32) mx = fmaxf(mx, p[i]);
        #pragma unroll
        for (int o = 16; o; o >>= 1) mx = fmaxf(mx, __shfl_xor_sync(~0u, mx, o));
        float sm = 0.f;
        for (int i = lane; i < 1024; i += 32) sm += expf(p[i] - mx);
        #pragma unroll
        for (int o = 16; o; o >>= 1) sm += __shfl_xor_sync(~0u, sm, o);
        if (lane == 0) { g_smx[row] = mx; g_smi[row] = 1.f / sm; }
    }
}

// ---------------- K2b: BN finalize + fp16 conversion (1024 blocks) ------------
__global__ __launch_bounds__(256) void k_conv(
    const float* __restrict__ bnw_q, const float* __restrict__ bnb_q,
    const float* __restrict__ bnw_v, const float* __restrict__ bnb_v)
{
    int blk = blockIdx.x;
    int tid = threadIdx.x;
    int ch = blk >> 3, part = blk & 7;
    int b0 = part * 4;
    __shared__ float s_sc, s_sh;
    if (tid == 0) {
        float s = 0.f, s2 = 0.f;
        #pragma unroll
        for (int p = 0; p < 8; p++) { s += g_bnp[ch][p][0]; s2 += g_bnp[ch][p][1]; }
        float inv = 1.f / (float)(BB * NN);
        float mean = s * inv;
        float var = s2 * inv - mean * mean;
        float w, bsh;
        if (ch < 64) { w = bnw_q[ch]; bsh = bnb_q[ch]; }
        else         { w = bnw_v[ch - 64]; bsh = bnb_v[ch - 64]; }
        float sc = w * rsqrtf(var + EPSB);
        s_sc = sc;
        s_sh = bsh - mean * sc;
    }
    __syncthreads();
    float sc = s_sc, sh = s_sh;

    if (ch < 64) {
        const float* src = g_q + (size_t)ch * NN;
        #pragma unroll
        for (int bb = 0; bb < 4; bb++) {
            int b = b0 + bb;
            const float4* p = reinterpret_cast<const float4*>(src + ((size_t)(b * 64) << 10));
            float4 v = p[tid];
            __half2 h0 = __floats2half2_rn(v.x * sc + sh, v.y * sc + sh);
            __half2 h1 = __floats2half2_rn(v.z * sc + sh, v.w * sc + sh);
            uint2 pk = make_uint2(*reinterpret_cast<uint32_t*>(&h0), *reinterpret_cast<uint32_t*>(&h1));
            *reinterpret_cast<uint2*>(&g_qh[(((size_t)(b * 64 + ch)) << 10) + tid * 4]) = pk;
        }
    } else {
        int v_ch = ch - 64;
        const float* src = g_v + (size_t)v_ch * NN;
        #pragma unroll
        for (int bb = 0; bb < 4; bb++) {
            int b = b0 + bb;
            const float4* p = reinterpret_cast<const float4*>(src + ((size_t)(b * 64) << 10));
            float4 v = p[tid];
            __half2 h0 = __floats2half2_rn(v.x * sc + sh, v.y * sc + sh);
            __half2 h1 = __floats2half2_rn(v.z * sc + sh, v.w * sc + sh);
            uint2 pk = make_uint2(*reinterpret_cast<uint32_t*>(&h0), *reinterpret_cast<uint32_t*>(&h1));
            int bv = b * 64 + v_ch;
            int n = tid * 4;
            *reinterpret_cast<uint2*>(&g_vh[(((size_t)bv) << 10) + n]) = pk;
            // swizzled tiled copy: [ch16][bvt8] 256x64 tiles; 8B block stays contiguous under sw128
            int mch = n >> 6, ml = n & 63;
            int bvt = bv >> 8, bvl = bv & 255;
            char* tile = (char*)g_vhs + (((size_t)mch * 8 + bvt) * 32768);
            *reinterpret_cast<uint2*>(tile + sw128(bvl * 128 + ml * 2)) = pk;
        }
    }
}

// ---------------- K3: lambda_c partials (stream 2, overlaps gemm) -------------
__global__ __launch_bounds__(256) void k_lambdac()
{
    int b = blockIdx.x;
    int part = blockIdx.y;
    int nc = part * 128;
    int tid = threadIdx.x;
    int s = tid >> 6, v = tid & 63;
    __shared__ float sbuf[16 * 128 + 128 * 65];
    __shared__ float s_mx[16], s_mi[16];
    float* sm_s = sbuf;
    float* vs_s = sbuf + 16 * 128;

    if (tid < 16) { s_mx[tid] = g_smx[b * 16 + tid]; s_mi[tid] = g_smi[b * 16 + tid]; }
    __syncthreads();

    for (int i = tid; i < 16 * 128; i += 256) {
        int k = i >> 7, nn = i & 127;
        float raw = g_k[(((size_t)b * 16 + k) << 10) + nc + nn];
        sm_s[k * 128 + nn] = expf(raw - s_mx[k]) * s_mi[k];
    }
    for (int i = tid; i < 64 * 128; i += 256) {
        int vv = i >> 7, nn = i & 127;
        vs_s[nn * 65 + vv] = __half2float(g_vh[(((size_t)b * 64 + vv) << 10) + nc + nn]);
    }
    __syncthreads();
    float acc[16] = {};
    for (int nn = s * 32; nn < s * 32 + 32; nn++) {
        float vv = vs_s[nn * 65 + v];
        #pragma unroll
        for (int k = 0; k < 16; k++) acc[k] += sm_s[k * 128 + nn] * vv;
    }
    __syncthreads();
    #pragma unroll
    for (int k = 0; k < 16; k++) sbuf[s * 1024 + k * 64 + v] = acc[k];
    __syncthreads();
    for (int e = tid; e < 1024; e += 256)
        g_lcp[part][b * 1024 + e] = sbuf[e] + sbuf[1024 + e] + sbuf[2048 + e] + sbuf[3072 + e];
}

// ---------------- K5: lambda_p GEMM (bulk loads + deferred refill) ------------
#define GEMM_SMEM (1024 + 3 * 65536)

__global__ __launch_bounds__(256) void k_gemm(const float* __restrict__ emb)
{
#if USE_TC
    extern __shared__ char dsm[];
    __shared__ __align__(16) uint64_t s_full[3], s_mma[3];
    __shared__ uint32_t s_tmem;

    int tid = threadIdx.x;
    int wid = tid >> 5, lane = tid & 31;
    int kg = blockIdx.z;
    int ntb = blockIdx.x;
    int bvt = blockIdx.y;
    int n0 = ntb * 128;
    int bv0 = bvt * 256;

    int y0 = ntb * 4;
    int c_lo = (y0 > 11) ? ((y0 - 11) >> 1) : 0;
    int c_hi = min(15, (y0 + 14) >> 1);
    int nch = c_hi - c_lo + 1;     // 8..14

    uint32_t raw = smem_u32(dsm);
    uint32_t abase = (raw + 1023) & ~1023u;

    if (wid == 0) { TC_ALLOC(smem_u32(&s_tmem), 512); TC_RELINQ(); }
    if (tid == 0) {
        #pragma unroll
        for (int s = 0; s < 3; s++) { MBAR_INIT(smem_u32(&s_full[s]), 1); MBAR_INIT(smem_u32(&s_mma[s]), 1); }
    }
    __syncthreads();
    uint32_t tmem = s_tmem;

    const uint32_t idesc = (1u << 4) | (32u << 17) | (8u << 24);

    if (tid == 0) {
        const char* Tb = (const char*)g_T;
        const char* Vb = (const char*)g_vhs;
        int fph[3] = {0, 0, 0}, mph[3] = {0, 0, 0};

        #define GEMM_LOAD(ch, s) do {                                                     \
            uint32_t _fb = smem_u32(&s_full[s]);                                          \
            uint32_t _sb = abase + (s) * 65536;                                           \
            MBAR_EXPECT_TX(_fb, 65536u);                                                  \
            bulkcp(_sb,          Tb + (((size_t)(2 * kg)     * 16 + (ch)) * 8 + ntb) * 16384, 16384, _fb); \
            bulkcp(_sb + 16384,  Tb + (((size_t)(2 * kg + 1) * 16 + (ch)) * 8 + ntb) * 16384, 16384, _fb); \
            bulkcp(_sb + 32768,  Vb + (((size_t)(ch) * 8 + bvt) * 32768), 32768, _fb);    \
        } while (0)

        GEMM_LOAD(c_lo + 0, 0);
        GEMM_LOAD(c_lo + 1, 1);
        GEMM_LOAD(c_lo + 2, 2);

        for (int ci = 0; ci < nch; ci++) {
            int s = ci - (ci / 3) * 3;
            MBAR_WAIT(smem_u32(&s_full[s]), fph[s]); fph[s] ^= 1;
            uint32_t sb = abase + s * 65536;
            uint64_t a0 = mk_desc(sb);
            uint64_t a1 = mk_desc(sb + 16384);
            uint64_t bd = mk_desc(sb + 32768);
            #pragma unroll
            for (int ks = 0; ks < 4; ks++) {
                uint32_t en = (ci | ks) != 0;
                mma_f16_ss(tmem,       a0 + ks * 2, bd + ks * 2, idesc, en);
                mma_f16_ss(tmem + 256, a1 + ks * 2, bd + ks * 2, idesc, en);
            }
            TC_COMMIT(smem_u32(&s_mma[s]));
            if (ci >= 1 && ci + 2 < nch) {
                int sp = (ci - 1) - ((ci - 1) / 3) * 3;
                MBAR_WAIT(smem_u32(&s_mma[sp]), mph[sp]); mph[sp] ^= 1;
                GEMM_LOAD(c_lo + ci + 2, sp);
            }
        }
        MBAR_WAIT(smem_u32(&s_mma[0]), mph[0]);
        MBAR_WAIT(smem_u32(&s_mma[1]), mph[1]);
        MBAR_WAIT(smem_u32(&s_mma[2]), mph[2]);
        #undef GEMM_LOAD
    }
    __syncthreads();
    TC_FENCE_AFTER();

    int t = wid >> 2;
    int kk = 2 * kg + t;
    int n_g = n0 + (wid & 3) * 32 + lane;
    for (int c0 = 0; c0 < 256; c0 += 32) {
        uint32_t r[32];
        TC_LD_X32(r, tmem + t * 256 + c0);
        TC_WAIT_LD();
        int bvb = bv0 + c0;
        int b = bvb >> 6, vb = bvb & 63;
        uint32_t h2[16];
        #pragma unroll
        for (int j = 0; j < 16; j++) {
            __half2 h = __floats2half2_rn(__uint_as_float(r[2 * j]), __uint_as_float(r[2 * j + 1]));
            h2[j] = *reinterpret_cast<uint32_t*>(&h);
        }
        __half* dst = g_lph + ((((size_t)(b * 16 + kk) << 10) + n_g) << 6) + vb;
        uint4* d4 = reinterpret_cast<uint4*>(dst);
        #pragma unroll
        for (int q4 = 0; q4 < 4; q4++)
            d4[q4] = make_uint4(h2[4 * q4], h2[4 * q4 + 1], h2[4 * q4 + 2], h2[4 * q4 + 3]);
    }
    __syncthreads();
    if (tid == 0) {
        #pragma unroll
        for (int s = 0; s < 3; s++) { MBAR_INVAL(smem_u32(&s_full[s])); MBAR_INVAL(smem_u32(&s_mma[s])); }
    }
    __syncthreads();
    if (wid == 0) TC_DEALLOC(tmem, 512);

#else  // ---- fallback: scalar direct conv (compile-only; grid 8x8x8 = 512) ----
    extern __shared__ char dsm[];
    float* img = (float*)dsm;
    float* Es  = img + 54 * 55;
    int tid = threadIdx.x;
    int bid = blockIdx.x + blockIdx.y * 8 + blockIdx.z * 64;

    for (int i = tid; i < 16 * 529; i += 256) Es[i] = emb[i];

    for (int pair = 0; pair < 4; pair++) {
        int bv = bid * 4 + pair;
        int b = bv >> 6, v = bv & 63;
        __syncthreads();
        for (int i = tid; i < 54 * 55; i += 256) img[i] = 0.f;
        __syncthreads();
        float vsc = 1.f, vsh = 0.f;   // fallback path unused on HW
        const float* src = g_v + ((size_t)bv << 10);
        for (int i = tid; i < 1024; i += 256) {
            int y = i >> 5, x = i & 31;
            img[(y + PADL) * 55 + x + PADL] = src[i] * vsc + vsh;
        }
        __syncthreads();

        for (int it = 0; it < 4; it++) {
            int task = tid + 256 * it;
            int k = task >> 6;
            int rh = task & 63;
            int row = rh >> 1;
            int xb = (rh & 1) << 4;
            float acc[16] = {};
            const float* ek = Es + k * 529;
            #pragma unroll 1
            for (int i = 0; i < RR; i++) {
                const float* rp = img + (row + i) * 55 + xb;
                float r[38];
                #pragma unroll
                for (int tt = 0; tt < 38; tt++) r[tt] = rp[tt];
                const float* ept = ek + i * RR;
                #pragma unroll
                for (int j = 0; j < RR; j++) {
                    float e = ept[j];
                    #pragma unroll
                    for (int x = 0; x < 16; x++) acc[x] += e * r[j + x];
                }
            }
            int nbase = row * 32 + xb;
            __half* o = g_lph + ((((size_t)(b * 16 + k) << 10) + nbase) << 6) + v;
            #pragma unroll
            for (int x = 0; x < 16; x++) o[(size_t)x << 6] = __float2half(acc[x]);
        }
    }
#endif
}

// ---------------- K6: final contraction (coalesced reads AND writes) ----------
#define FINAL_SMEM (256 * 65 * 4 + 64 * 64 * 2 + 16 * 64 * 4)   // y_s | q_s | lc_s

__global__ __launch_bounds__(256) void k_final(const float* __restrict__ gamma,
                                               float* __restrict__ out)
{
    extern __shared__ char fsm[];
    float* y_s  = (float*)fsm;
    __half* q_s = (__half*)(fsm + 256 * 65 * 4);
    float* lc_s = (float*)(fsm + 256 * 65 * 4 + 64 * 64 * 2);

    int b = blockIdx.y;
    int n0 = blockIdx.x * 64;
    int tid = threadIdx.x;
    int n_loc = tid >> 2;
    int vg = tid & 3;
    int v0 = vg * 16;
    int n = n0 + n_loc;

    for (int i = tid; i < 1024; i += 256) {
        float sum = 0.f;
        #pragma unroll
        for (int p = 0; p < 8; p++) sum += g_lcp[p][b * 1024 + i];
        lc_s[i] = sum;
    }
    for (int i = tid; i < 64 * 32; i += 256) {
        int ch = i >> 5, n2 = (i & 31) * 2;
        *reinterpret_cast<__half2*>(&q_s[ch * 64 + n2]) =
            *reinterpret_cast<const __half2*>(&g_qh[(((size_t)b * 64 + ch) << 10) + n0 + n2]);
    }
    __syncthreads();

    float y[4][16] = {};
    const __half* lpb = g_lph + (((size_t)b * 16) << 16);
    for (int k = 0; k < 16; k++) {
        const uint4* lp = reinterpret_cast<const uint4*>(
            lpb + (((size_t)k << 10) + n) * 64 + v0);
        uint4 ra = lp[0], rb = lp[1];
        __half2 h2[8];
        h2[0] = *reinterpret_cast<__half2*>(&ra.x); h2[1] = *reinterpret_cast<__half2*>(&ra.y);
        h2[2] = *reinterpret_cast<__half2*>(&ra.z); h2[3] = *reinterpret_cast<__half2*>(&ra.w);
        h2[4] = *reinterpret_cast<__half2*>(&rb.x); h2[5] = *reinterpret_cast<__half2*>(&rb.y);
        h2[6] = *reinterpret_cast<__half2*>(&rb.z); h2[7] = *reinterpret_cast<__half2*>(&rb.w);
        float lam[16];
        #pragma unroll
        for (int j = 0; j < 8; j++) {
            float2 f = __half22float2(h2[j]);
            lam[2 * j] = f.x; lam[2 * j + 1] = f.y;
        }
        #pragma unroll
        for (int jj = 0; jj < 16; jj++) lam[jj] += lc_s[k * 64 + v0 + jj];
        #pragma unroll
        for (int h = 0; h < 4; h++) {
            float qh = __half2float(q_s[(h * 16 + k) * 64 + n_loc]);
            #pragma unroll
            for (int jj = 0; jj < 16; jj++) y[h][jj] += qh * lam[jj];
        }
    }
    float gm = 1.f + gamma[0];
    #pragma unroll
    for (int h = 0; h < 4; h++)
        #pragma unroll
        for (int jj = 0; jj < 16; jj++)
            y_s[(h * 64 + v0 + jj) * 65 + n_loc] = y[h][jj] * gm;
    __syncthreads();

    for (int it = 0; it < 64; it++) {
        int idx = it * 256 + tid;
        int ch = idx >> 6, nl = idx & 63;
        out[(((size_t)b * 256 + ch) << 10) + n0 + nl] = y_s[ch * 65 + nl];
    }
}

// ---------------- launch: dual-stream fork/join ----------------
extern "C" void kernel_launch(void* const* d_in, const int* in_sizes, int n_in,
                              void* d_out, int out_size)
{
    const float* x      = (const float*)d_in[0];
    const float* Wq     = (const float*)d_in[1];
    const float* bn_q_w = (const float*)d_in[2];
    const float* bn_q_b = (const float*)d_in[3];
    const float* Wk     = (const float*)d_in[4];
    const float* Wv     = (const float*)d_in[5];
    const float* bn_v_w = (const float*)d_in[6];
    const float* bn_v_b = (const float*)d_in[7];
    const float* emb    = (const float*)d_in[8];
    const float* gamma  = (const float*)d_in[9];
    float* out = (float*)d_out;

    cudaFuncSetAttribute(k_gemm, cudaFuncAttributeMaxDynamicSharedMemorySize, GEMM_SMEM);
    cudaFuncSetAttribute(k_proj, cudaFuncAttributeMaxDynamicSharedMemorySize, PROJ_SMEM);
    cudaFuncSetAttribute(k_final, cudaFuncAttributeMaxDynamicSharedMemorySize, FINAL_SMEM);

    cudaStream_t s2;
    cudaStreamCreateWithFlags(&s2, cudaStreamNonBlocking);
    cudaEvent_t e0, eT, eS, eL;
    cudaEventCreateWithFlags(&e0, cudaEventDisableTiming);
    cudaEventCreateWithFlags(&eT, cudaEventDisableTiming);
    cudaEventCreateWithFlags(&eS, cudaEventDisableTiming);
    cudaEventCreateWithFlags(&eL, cudaEventDisableTiming);

    // fork: buildT on s2, overlapping the x-path
    cudaEventRecord(e0, 0);
    cudaStreamWaitEvent(s2, e0, 0);
    k_prep_T<<<32768, 256, 0, s2>>>(emb);
    cudaEventRecord(eT, s2);

    k_prep_x<<<2208, 256>>>(x, Wq, Wk, Wv);
    k_proj<<<dim3(4, 32), 256, PROJ_SMEM>>>();
    k_stats1<<<1088, 256>>>();
    k_conv<<<1024, 256>>>(bn_q_w, bn_q_b, bn_v_w, bn_v_b);
    cudaEventRecord(eS, 0);

    // fork: lambda_c on s2, overlapping the gemm
    cudaStreamWaitEvent(s2, eS, 0);
    k_lambdac<<<dim3(32, 8), 256, 0, s2>>>();
    cudaEventRecord(eL, s2);

    cudaStreamWaitEvent(0, eT, 0);
    k_gemm<<<dim3(8, 8, 8), 256, GEMM_SMEM>>>(emb);
    cudaStreamWaitEvent(0, eL, 0);
    k_final<<<dim3(16, 32), 256, FINAL_SMEM>>>(gamma, out);
}